// round 6
// baseline (speedup 1.0000x reference)
#include <cuda_runtime.h>
#include <cuda_bf16.h>
#include <cstdint>

#define S_LEN 8192
#define NBATCH 8
#define DIM 128
#define NB 32
#define NROWS (NBATCH*S_LEN)
#define LDE 136      // bf16 elems per 272B operand row
#define LDS2 68      // f32 staging row

// ---------------- scratch (static device arrays; allocation-free rule) -----
__device__ __align__(16) __nv_bfloat16 g_x_hi[(size_t)NROWS*DIM];
__device__ __align__(16) __nv_bfloat16 g_x_lo[(size_t)NROWS*DIM];
__device__ __align__(16) __nv_bfloat16 g_q_hi[(size_t)NROWS*DIM];
__device__ __align__(16) __nv_bfloat16 g_q_lo[(size_t)NROWS*DIM];
__device__ __align__(16) __nv_bfloat16 g_k_hi[(size_t)NBATCH*DIM*S_LEN]; // [b][h][t]
__device__ __align__(16) __nv_bfloat16 g_k_lo[(size_t)NBATCH*DIM*S_LEN];
__device__ __align__(16) __nv_bfloat16 g_v_hi[(size_t)NBATCH*DIM*S_LEN];
__device__ __align__(16) __nv_bfloat16 g_v_lo[(size_t)NBATCH*DIM*S_LEN];
__device__ __align__(16) float g_C[(size_t)NBATCH*NB*DIM*DIM];           // C'[hv][hk]
__device__ __align__(16) __nv_bfloat16 g_w_hi[3*DIM*DIM];
__device__ __align__(16) __nv_bfloat16 g_w_lo[3*DIM*DIM];

// ---------------- helpers ---------------------------------------------------
__device__ __forceinline__ unsigned smem_u32(const void* p){
    unsigned a; asm("{ .reg .u64 t; cvta.to.shared.u64 t, %1; cvt.u32.u64 %0, t; }":"=r"(a):"l"(p)); return a;
}
__device__ __forceinline__ void ldm4(unsigned* r, unsigned addr){
    asm volatile("ldmatrix.sync.aligned.m8n8.x4.shared.b16 {%0,%1,%2,%3}, [%4];"
        : "=r"(r[0]),"=r"(r[1]),"=r"(r[2]),"=r"(r[3]) : "r"(addr));
}
__device__ __forceinline__ void mma16816(float* d, const unsigned* a, unsigned b0, unsigned b1){
    asm volatile("mma.sync.aligned.m16n8k16.row.col.f32.bf16.bf16.f32 "
        "{%0,%1,%2,%3}, {%4,%5,%6,%7}, {%8,%9}, {%0,%1,%2,%3};"
        : "+f"(d[0]),"+f"(d[1]),"+f"(d[2]),"+f"(d[3])
        : "r"(a[0]),"r"(a[1]),"r"(a[2]),"r"(a[3]), "r"(b0),"r"(b1));
}
__device__ __forceinline__ void cpa(unsigned d, const void* s){
    asm volatile("cp.async.cg.shared.global [%0], [%1], 16;"::"r"(d),"l"(s));
}
#define CPC() asm volatile("cp.async.commit_group;":::"memory")
#define CPW(n) asm volatile("cp.async.wait_group %0;"::"n"(n):"memory")

// 32x32 warp tile: acc[2][4][4]
template<int LD, int KS>
__device__ __forceinline__ void warp_pass(unsigned aB, unsigned bB,
                                          float acc[2][4][4], int wr, int wc, int lane){
    unsigned aAddr = aB + (unsigned)((wr*32 + (lane&15))*LD) + ((lane>>4)<<4);
    unsigned bAddr = bB + (unsigned)((wc*32 + (lane&7) + ((lane>>4)<<3))*LD) + (((lane>>3)&1)<<4);
#pragma unroll
    for(int ks=0; ks<KS; ks++){
        unsigned a0[4], a1[4], br[2][4];
        ldm4(a0, aAddr + ks*32);
        ldm4(a1, aAddr + 16*LD + ks*32);
#pragma unroll
        for(int n2=0; n2<2; n2++) ldm4(br[n2], bAddr + n2*16*LD + ks*32);
#pragma unroll
        for(int nt=0; nt<4; nt++){
            unsigned b0 = br[nt>>1][(nt&1)*2], b1 = br[nt>>1][(nt&1)*2+1];
            mma16816(acc[0][nt], a0, b0, b1);
            mma16816(acc[1][nt], a1, b0, b1);
        }
    }
}
__device__ __forceinline__ void zacc(float acc[2][4][4]){
#pragma unroll
    for(int a=0;a<2;a++)
#pragma unroll
    for(int b=0;b<4;b++){acc[a][b][0]=acc[a][b][1]=acc[a][b][2]=acc[a][b][3]=0.f;}
}
__device__ __forceinline__ void stage_acc(float* stag, float acc[2][4][4], int wr, int wc, int lane){
    int rb = wr*32 + (lane>>2), cb = wc*32 + (lane&3)*2;
#pragma unroll
    for(int mt=0; mt<2; mt++)
#pragma unroll
    for(int nt=0; nt<4; nt++){
        int r = rb + mt*16, c = cb + nt*8;
        *(float2*)&stag[r*LDS2+c]     = make_float2(acc[mt][nt][0], acc[mt][nt][1]);
        *(float2*)&stag[(r+8)*LDS2+c] = make_float2(acc[mt][nt][2], acc[mt][nt][3]);
    }
}
__device__ __forceinline__ void cvt64(const float* s, __nv_bfloat16* dh, __nv_bfloat16* dl){
#pragma unroll
    for(int g=0; g<8; g++){
        float4 a=((const float4*)s)[2*g], b=((const float4*)s)[2*g+1];
        float f[8]={a.x,a.y,a.z,a.w,b.x,b.y,b.z,b.w};
        __align__(16) __nv_bfloat16 h[8], l[8];
#pragma unroll
        for(int i=0;i<8;i++){ h[i]=__float2bfloat16_rn(f[i]); l[i]=__float2bfloat16_rn(f[i]-__bfloat162float(h[i])); }
        ((uint4*)dh)[g]=*(const uint4*)h; ((uint4*)dl)[g]=*(const uint4*)l;
    }
}
__device__ __forceinline__ void cvt32(const float* f, __nv_bfloat16* dh, __nv_bfloat16* dl){
#pragma unroll
    for(int g=0; g<4; g++){
        __align__(16) __nv_bfloat16 h[8], l[8];
#pragma unroll
        for(int i=0;i<8;i++){
            float v=f[g*8+i];
            h[i]=__float2bfloat16_rn(v); l[i]=__float2bfloat16_rn(v-__bfloat162float(h[i]));
        }
        ((uint4*)dh)[g]=*(const uint4*)h; ((uint4*)dl)[g]=*(const uint4*)l;
    }
}

// ============== K0w: pre-convert W ==========================================
__global__ void k0w(const float* __restrict__ Wq, const float* __restrict__ Wk,
                    const float* __restrict__ Wv){
    const float* W = blockIdx.x==0?Wq:(blockIdx.x==1?Wk:Wv);
    int h = threadIdx.x;
    size_t o = (size_t)blockIdx.x*16384 + (size_t)h*128;
    cvt64(W + (size_t)h*128,      g_w_hi+o,    g_w_lo+o);
    cvt64(W + (size_t)h*128 + 64, g_w_hi+o+64, g_w_lo+o+64);
}
// ============== K0x: pre-convert x ==========================================
__global__ void k0x(const float* __restrict__ x){
    size_t i = ((size_t)blockIdx.x*256 + threadIdx.x)*4;
    float4 v = *(const float4*)(x+i);
    float f[4]={v.x,v.y,v.z,v.w};
    __align__(8) __nv_bfloat16 h[4], l[4];
#pragma unroll
    for(int j=0;j<4;j++){ h[j]=__float2bfloat16_rn(f[j]); l[j]=__float2bfloat16_rn(f[j]-__bfloat162float(h[j])); }
    *(uint2*)(g_x_hi+i)=*(const uint2*)h;
    *(uint2*)(g_x_lo+i)=*(const uint2*)l;
}

// ============== K1: qkv projection (128 rows x 64-col half) =================
#define O1_AH 0
#define O1_AL 34816
#define O1_BH 69632
#define O1_BL 87040
#define O1_BIAS 104448
#define SM1 105984

__device__ __forceinline__ void k1_prefetch_w(unsigned sb, int m, int ch, int tid){
#pragma unroll
    for(int i=0;i<8;i++){
        int c = tid + 256*i;
        int op = c>>10, e=c&1023, row=e>>4, col8=e&15;
        cpa(sb + O1_BH + (unsigned)op*17408u + (unsigned)(row*272 + col8*16),
            (op? g_w_lo : g_w_hi) + (size_t)m*16384 + (size_t)(ch*64+row)*128 + col8*8);
    }
}
__global__ __launch_bounds__(256,2) void k1(const float* __restrict__ bq,
    const float* __restrict__ bk, const float* __restrict__ bv)
{
    extern __shared__ char sm[];
    unsigned sb = smem_u32(sm);
    const int tid=threadIdx.x, lane=tid&31, warp=tid>>5, wr=warp>>1, wc=warp&1;
    const int r0=blockIdx.x*128, ch=blockIdx.y;
    float* bias_s=(float*)(sm+O1_BIAS);
#pragma unroll
    for(int i=0;i<16;i++){   // A: 128 rows hi/lo
        int c = tid + 256*i;
        int op = c>>11, e=c&2047, row=e>>4, col8=e&15;
        cpa(sb + (unsigned)op*34816u + (unsigned)(row*272 + col8*16),
            (op? g_x_lo : g_x_hi) + (size_t)(r0+row)*128 + col8*8);
    }
    k1_prefetch_w(sb, 0, ch, tid);
    CPC();
    if(tid<128){ bias_s[tid]=bq[tid]; bias_s[128+tid]=bk[tid]; bias_s[256+tid]=bv[tid]; }
    for(int m=0;m<3;m++){
        CPW(0); __syncthreads();
        float acc[2][4][4]; zacc(acc);
        warp_pass<272,8>(sb+O1_AH, sb+O1_BH, acc, wr, wc, lane);
        warp_pass<272,8>(sb+O1_AH, sb+O1_BL, acc, wr, wc, lane);
        warp_pass<272,8>(sb+O1_AL, sb+O1_BH, acc, wr, wc, lane);
        __syncthreads();
        float* stag=(float*)(sm+O1_BH);   // overlay consumed B
        stage_acc(stag, acc, wr, wc, lane);
        __syncthreads();
        if(m==0){
            const int r=tid>>1, hf=tid&1;
            float tmp[32];
#pragma unroll
            for(int j=0;j<32;j++) tmp[j]=stag[r*LDS2+hf*32+j]+bias_s[ch*64+hf*32+j];
            size_t off=(size_t)(r0+r)*128 + ch*64 + hf*32;
            cvt32(tmp, g_q_hi+off, g_q_lo+off);
        } else {
            const int hl=tid&63, tp=tid>>6, h=ch*64+hl;
            const float bsv=bias_s[m*128+h];
            float tmp[32];
#pragma unroll
            for(int j=0;j<32;j++) tmp[j]=stag[(tp*32+j)*LDS2 + hl]+bsv;
            size_t off=(size_t)((r0>>13)*128+h)*S_LEN + (r0&8191) + tp*32;
            if(m==1) cvt32(tmp, g_k_hi+off, g_k_lo+off);
            else     cvt32(tmp, g_v_hi+off, g_v_lo+off);
        }
        __syncthreads();
        if(m<2){ k1_prefetch_w(sb, m+1, ch, tid); CPC(); }
    }
}

// ============== K2: C'_m (128 v-dims x 64 k-dim half), K=256 pipelined ======
#define O2_VH 0
#define O2_VL 18432
#define O2_KH 36864
#define O2_KL 46080
#define K2_BUF 55296
#define SM2 110592

__device__ __forceinline__ void k2_prefetch(unsigned buf, int b, int ch, int t0, int tid){
#pragma unroll
    for(int i=0;i<12;i++){
        int c = tid + 256*i;
        if(c<2048){
            int op=c>>10, e=c&1023, row=e>>3, col8=e&7;
            cpa(buf + (unsigned)op*18432u + (unsigned)(row*144 + col8*16),
                (op? g_v_lo : g_v_hi) + (size_t)(b*128+row)*S_LEN + t0 + col8*8);
        } else {
            int d=c-2048, op=d>>9, e=d&511, row=e>>3, col8=e&7;
            cpa(buf + 36864u + (unsigned)op*9216u + (unsigned)(row*144 + col8*16),
                (op? g_k_lo : g_k_hi) + (size_t)(b*128+ch*64+row)*S_LEN + t0 + col8*8);
        }
    }
}
__global__ __launch_bounds__(256,2) void k2()
{
    extern __shared__ char sm[];
    unsigned sb=smem_u32(sm);
    const int tid=threadIdx.x, lane=tid&31, warp=tid>>5, wr=warp>>1, wc=warp&1;
    const int b=blockIdx.x>>5, mc=blockIdx.x&31, ch=blockIdx.y;
    const int t0=mc*256;
    k2_prefetch(sb, b, ch, t0, tid); CPC();
    float acc[2][4][4]; zacc(acc);
    for(int qt=0; qt<4; qt++){
        unsigned buf = (qt&1)? K2_BUF : 0u;
        if(qt<3){ k2_prefetch(sb + ((qt&1)?0u:K2_BUF), b, ch, t0+(qt+1)*64, tid); CPC(); CPW(1); }
        else CPW(0);
        __syncthreads();
        warp_pass<144,4>(sb+buf+O2_VH, sb+buf+O2_KH, acc, wr, wc, lane);
        warp_pass<144,4>(sb+buf+O2_VH, sb+buf+O2_KL, acc, wr, wc, lane);
        warp_pass<144,4>(sb+buf+O2_VL, sb+buf+O2_KH, acc, wr, wc, lane);
        __syncthreads();
    }
    float* stag=(float*)sm;
    stage_acc(stag, acc, wr, wc, lane);
    __syncthreads();
    const int r=tid>>1, hf=tid&1;
    float* dst=g_C+((size_t)(b*32+mc)*128+r)*128+ch*64+hf*32;
#pragma unroll
    for(int g=0; g<8; g++){
        float4 o=make_float4(stag[r*LDS2+hf*32+g*4],stag[r*LDS2+hf*32+g*4+1],
                             stag[r*LDS2+hf*32+g*4+2],stag[r*LDS2+hf*32+g*4+3]);
        ((float4*)dst)[g]=o;
    }
}

// ============== K3: out = scale*(q @ Csum^T - edges), 64-col half ===========
#define O3_AH 0
#define O3_AL 34816
#define O3_BH 69632
#define O3_BL 87040
#define O3_EXT 104448
#define SM3 107008

__device__ __forceinline__ void k3_prefetch_q(unsigned sb, size_t qrow0, int tid){
#pragma unroll
    for(int i=0;i<16;i++){
        int c = tid + 256*i;
        int op = c>>11, e=c&2047, row=e>>4, col8=e&15;
        cpa(sb + (unsigned)op*34816u + (unsigned)(row*272 + col8*16),
            (op? g_q_lo : g_q_hi) + (qrow0+row)*128 + col8*8);
    }
}
__global__ __launch_bounds__(256,2) void k3(float* __restrict__ out)
{
    extern __shared__ char sm[];
    unsigned sb=smem_u32(sm);
    const int tid=threadIdx.x, lane=tid&31, warp=tid>>5, wr=warp>>1, wc=warp&1;
    const int b=blockIdx.x>>5, n=blockIdx.x&31, ch=blockIdx.y;
    __nv_bfloat16* Ah=(__nv_bfloat16*)(sm+O3_AH); __nv_bfloat16* Al=(__nv_bfloat16*)(sm+O3_AL);
    __nv_bfloat16* Bh=(__nv_bfloat16*)(sm+O3_BH); __nv_bfloat16* Bl=(__nv_bfloat16*)(sm+O3_BL);
    float* keL=(float*)(sm+O3_EXT);      float* keR=(float*)(sm+O3_EXT+512);
    float* veL=(float*)(sm+O3_EXT+1024); float* veR=(float*)(sm+O3_EXT+1280);
    float* dls=(float*)(sm+O3_EXT+1536); float* drs=(float*)(sm+O3_EXT+2048);
    const size_t qbase=(size_t)b*S_LEN + n*256;
    k3_prefetch_q(sb, qbase, tid); CPC();
    { // B rows (output cols = hv) = Csum over valid chunks, 64 rows this half
        const int mlo=(n>0)?n-1:0, mhi=(n<31)?n+1:31;
        const int r2=tid>>2, q4=tid&3;
        float s[32];
#pragma unroll
        for(int j=0;j<32;j++) s[j]=0.f;
        for(int mm=mlo; mm<=mhi; mm++){
            const float4* p=(const float4*)(g_C+((size_t)(b*32+mm)*128+ch*64+r2)*128+q4*32);
#pragma unroll
            for(int g=0; g<8; g++){ float4 v=p[g]; s[g*4]+=v.x; s[g*4+1]+=v.y; s[g*4+2]+=v.z; s[g*4+3]+=v.w; }
        }
        cvt32(s, Bh+r2*LDE+q4*32, Bl+r2*LDE+q4*32);
    }
    {
        int teL=n*256-256, teR=n*256+511;
        if(tid<128){
            size_t rb=(size_t)(b*128+tid)*S_LEN;
            keL[tid]=(n>0)? __bfloat162float(g_k_hi[rb+teL])+__bfloat162float(g_k_lo[rb+teL]):0.f;
            keR[tid]=(n<31)? __bfloat162float(g_k_hi[rb+teR])+__bfloat162float(g_k_lo[rb+teR]):0.f;
        } else {
            int j=tid-128;
            if(j<64){
                size_t rb=(size_t)(b*128+ch*64+j)*S_LEN;
                veL[j]=(n>0)? __bfloat162float(g_v_hi[rb+teL])+__bfloat162float(g_v_lo[rb+teL]):0.f;
                veR[j]=(n<31)? __bfloat162float(g_v_hi[rb+teR])+__bfloat162float(g_v_lo[rb+teR]):0.f;
            }
        }
    }
    const float scale=0.08838834764831845f;
    for(int half=0; half<2; half++){
        CPW(0); __syncthreads();
        const int r=tid>>1, hf=tid&1;
        {   // per-row edge dots
            float dl=0.f, dr=0.f;
#pragma unroll 16
            for(int c=0; c<64; c++){
                float q=__bfloat162float(Ah[r*LDE+hf*64+c])+__bfloat162float(Al[r*LDE+hf*64+c]);
                dl+=q*keL[hf*64+c]; dr+=q*keR[hf*64+c];
            }
            dl += __shfl_xor_sync(0xffffffffu, dl, 1);
            dr += __shfl_xor_sync(0xffffffffu, dr, 1);
            if(hf==0){ dls[r]=dl; drs[r]=dr; }
        }
        float acc[2][4][4]; zacc(acc);
        warp_pass<272,8>(sb+O3_AH, sb+O3_BH, acc, wr, wc, lane);
        warp_pass<272,8>(sb+O3_AH, sb+O3_BL, acc, wr, wc, lane);
        warp_pass<272,8>(sb+O3_AL, sb+O3_BH, acc, wr, wc, lane);
        __syncthreads();
        float* stag=(float*)sm;        // overlay A (consumed)
        stage_acc(stag, acc, wr, wc, lane);
        __syncthreads();
        const float dlv=dls[r], drv=drs[r];
        float* op=out+(qbase+half*128+r)*128+ch*64+hf*32;
#pragma unroll
        for(int g=0; g<8; g++){
            int c0=hf*32+g*4;
            float4 o;
            o.x=scale*(stag[r*LDS2+c0+0]-dlv*veL[c0+0]-drv*veR[c0+0]);
            o.y=scale*(stag[r*LDS2+c0+1]-dlv*veL[c0+1]-drv*veR[c0+1]);
            o.z=scale*(stag[r*LDS2+c0+2]-dlv*veL[c0+2]-drv*veR[c0+2]);
            o.w=scale*(stag[r*LDS2+c0+3]-dlv*veL[c0+3]-drv*veR[c0+3]);
            ((float4*)op)[g]=o;
        }
        __syncthreads();
        if(half==0){ k3_prefetch_q(sb, qbase+128, tid); CPC(); }
    }
}

// ---------------------------------------------------------------------------
extern "C" void kernel_launch(void* const* d_in, const int* in_sizes, int n_in,
                              void* d_out, int out_size)
{
    const float* x =(const float*)d_in[0];
    const float* Wq=(const float*)d_in[1]; const float* bq=(const float*)d_in[2];
    const float* Wk=(const float*)d_in[3]; const float* bk=(const float*)d_in[4];
    const float* Wv=(const float*)d_in[5]; const float* bv=(const float*)d_in[6];
    float* out=(float*)d_out;
    cudaFuncSetAttribute(k1, cudaFuncAttributeMaxDynamicSharedMemorySize, SM1);
    cudaFuncSetAttribute(k2, cudaFuncAttributeMaxDynamicSharedMemorySize, SM2);
    cudaFuncSetAttribute(k3, cudaFuncAttributeMaxDynamicSharedMemorySize, SM3);
    k0w<<<3,128>>>(Wq,Wk,Wv);
    k0x<<<NROWS*DIM/1024,256>>>(x);
    k1<<<dim3(NROWS/128,2),256,SM1>>>(bq,bk,bv);
    k2<<<dim3(NBATCH*NB,2),256,SM2>>>();
    k3<<<dim3(NBATCH*NB,2),256,SM3>>>(out);
}

// round 7
// speedup vs baseline: 1.0001x; 1.0001x over previous
#include <cuda_runtime.h>
#include <cuda_bf16.h>
#include <cstdint>

#define S_LEN 8192
#define NBATCH 8
#define DIM 128
#define NB 32
#define NROWS (NBATCH*S_LEN)
#define LDE 136      // bf16 elems per 272B operand row
#define LDS2 68      // f32 staging row

// ---------------- scratch (static device arrays; allocation-free rule) -----
__device__ __align__(16) __nv_bfloat16 g_q_hi[(size_t)NROWS*DIM];
__device__ __align__(16) __nv_bfloat16 g_q_lo[(size_t)NROWS*DIM];
__device__ __align__(16) __nv_bfloat16 g_k_hi[(size_t)NBATCH*DIM*S_LEN]; // [b][h][t]
__device__ __align__(16) __nv_bfloat16 g_k_lo[(size_t)NBATCH*DIM*S_LEN];
__device__ __align__(16) __nv_bfloat16 g_v_hi[(size_t)NBATCH*DIM*S_LEN];
__device__ __align__(16) __nv_bfloat16 g_v_lo[(size_t)NBATCH*DIM*S_LEN];
__device__ __align__(16) float g_C[(size_t)NBATCH*NB*DIM*DIM];           // C'[hv][hk]
__device__ __align__(16) __nv_bfloat16 g_w_hi[3*DIM*DIM];
__device__ __align__(16) __nv_bfloat16 g_w_lo[3*DIM*DIM];

// ---------------- helpers ---------------------------------------------------
__device__ __forceinline__ unsigned smem_u32(const void* p){
    unsigned a; asm("{ .reg .u64 t; cvta.to.shared.u64 t, %1; cvt.u32.u64 %0, t; }":"=r"(a):"l"(p)); return a;
}
__device__ __forceinline__ void ldm4(unsigned* r, unsigned addr){
    asm volatile("ldmatrix.sync.aligned.m8n8.x4.shared.b16 {%0,%1,%2,%3}, [%4];"
        : "=r"(r[0]),"=r"(r[1]),"=r"(r[2]),"=r"(r[3]) : "r"(addr));
}
__device__ __forceinline__ void mma16816(float* d, const unsigned* a, unsigned b0, unsigned b1){
    asm volatile("mma.sync.aligned.m16n8k16.row.col.f32.bf16.bf16.f32 "
        "{%0,%1,%2,%3}, {%4,%5,%6,%7}, {%8,%9}, {%0,%1,%2,%3};"
        : "+f"(d[0]),"+f"(d[1]),"+f"(d[2]),"+f"(d[3])
        : "r"(a[0]),"r"(a[1]),"r"(a[2]),"r"(a[3]), "r"(b0),"r"(b1));
}
__device__ __forceinline__ void cpa(unsigned d, const void* s){
    asm volatile("cp.async.cg.shared.global [%0], [%1], 16;"::"r"(d),"l"(s));
}
#define CPC() asm volatile("cp.async.commit_group;":::"memory")
#define CPW(n) asm volatile("cp.async.wait_group %0;"::"n"(n):"memory")

// 32x32 warp tile: acc[2][4][4]
template<int LD, int KS>
__device__ __forceinline__ void warp_pass(unsigned aB, unsigned bB,
                                          float acc[2][4][4], int wr, int wc, int lane){
    unsigned aAddr = aB + (unsigned)((wr*32 + (lane&15))*LD) + ((lane>>4)<<4);
    unsigned bAddr = bB + (unsigned)((wc*32 + (lane&7) + ((lane>>4)<<3))*LD) + (((lane>>3)&1)<<4);
#pragma unroll
    for(int ks=0; ks<KS; ks++){
        unsigned a0[4], a1[4], br[2][4];
        ldm4(a0, aAddr + ks*32);
        ldm4(a1, aAddr + 16*LD + ks*32);
#pragma unroll
        for(int n2=0; n2<2; n2++) ldm4(br[n2], bAddr + n2*16*LD + ks*32);
#pragma unroll
        for(int nt=0; nt<4; nt++){
            unsigned b0 = br[nt>>1][(nt&1)*2], b1 = br[nt>>1][(nt&1)*2+1];
            mma16816(acc[0][nt], a0, b0, b1);
            mma16816(acc[1][nt], a1, b0, b1);
        }
    }
}
__device__ __forceinline__ void zacc(float acc[2][4][4]){
#pragma unroll
    for(int a=0;a<2;a++)
#pragma unroll
    for(int b=0;b<4;b++){acc[a][b][0]=acc[a][b][1]=acc[a][b][2]=acc[a][b][3]=0.f;}
}
__device__ __forceinline__ void stage_acc(float* stag, float acc[2][4][4], int wr, int wc, int lane){
    int rb = wr*32 + (lane>>2), cb = wc*32 + (lane&3)*2;
#pragma unroll
    for(int mt=0; mt<2; mt++)
#pragma unroll
    for(int nt=0; nt<4; nt++){
        int r = rb + mt*16, c = cb + nt*8;
        *(float2*)&stag[r*LDS2+c]     = make_float2(acc[mt][nt][0], acc[mt][nt][1]);
        *(float2*)&stag[(r+8)*LDS2+c] = make_float2(acc[mt][nt][2], acc[mt][nt][3]);
    }
}
__device__ __forceinline__ void cvt64(const float* s, __nv_bfloat16* dh, __nv_bfloat16* dl){
#pragma unroll
    for(int g=0; g<8; g++){
        float4 a=((const float4*)s)[2*g], b=((const float4*)s)[2*g+1];
        float f[8]={a.x,a.y,a.z,a.w,b.x,b.y,b.z,b.w};
        __align__(16) __nv_bfloat16 h[8], l[8];
#pragma unroll
        for(int i=0;i<8;i++){ h[i]=__float2bfloat16_rn(f[i]); l[i]=__float2bfloat16_rn(f[i]-__bfloat162float(h[i])); }
        ((uint4*)dh)[g]=*(const uint4*)h; ((uint4*)dl)[g]=*(const uint4*)l;
    }
}
__device__ __forceinline__ void cvt32(const float* f, __nv_bfloat16* dh, __nv_bfloat16* dl){
#pragma unroll
    for(int g=0; g<4; g++){
        __align__(16) __nv_bfloat16 h[8], l[8];
#pragma unroll
        for(int i=0;i<8;i++){
            float v=f[g*8+i];
            h[i]=__float2bfloat16_rn(v); l[i]=__float2bfloat16_rn(v-__bfloat162float(h[i]));
        }
        ((uint4*)dh)[g]=*(const uint4*)h; ((uint4*)dl)[g]=*(const uint4*)l;
    }
}

// ============== K0w: pre-convert W ==========================================
__global__ void k0w(const float* __restrict__ Wq, const float* __restrict__ Wk,
                    const float* __restrict__ Wv){
    const float* W = blockIdx.x==0?Wq:(blockIdx.x==1?Wk:Wv);
    int h = threadIdx.x;
    size_t o = (size_t)blockIdx.x*16384 + (size_t)h*128;
    cvt64(W + (size_t)h*128,      g_w_hi+o,    g_w_lo+o);
    cvt64(W + (size_t)h*128 + 64, g_w_hi+o+64, g_w_lo+o+64);
}

// ============== K1: qkv projection (128 rows x 64-col half) =================
// grid (2, 512): blockIdx.x = column half -> paired CTAs share x rows via L2
#define O1_AH 0
#define O1_AL 34816
#define O1_BH 69632
#define O1_BL 87040
#define O1_BIAS 104448
#define SM1 105984

__device__ __forceinline__ void k1_prefetch_w(unsigned sb, int m, int ch, int tid){
#pragma unroll
    for(int i=0;i<8;i++){
        int c = tid + 256*i;
        int op = c>>10, e=c&1023, row=e>>4, col8=e&15;
        cpa(sb + O1_BH + (unsigned)op*17408u + (unsigned)(row*272 + col8*16),
            (op? g_w_lo : g_w_hi) + (size_t)m*16384 + (size_t)(ch*64+row)*128 + col8*8);
    }
}
__global__ __launch_bounds__(256,2) void k1(const float* __restrict__ x,
    const float* __restrict__ bq, const float* __restrict__ bk, const float* __restrict__ bv)
{
    extern __shared__ char sm[];
    unsigned sb = smem_u32(sm);
    const int tid=threadIdx.x, lane=tid&31, warp=tid>>5, wr=warp>>1, wc=warp&1;
    const int ch=blockIdx.x, r0=blockIdx.y*128;
    __nv_bfloat16* Ah=(__nv_bfloat16*)(sm+O1_AH); __nv_bfloat16* Al=(__nv_bfloat16*)(sm+O1_AL);
    float* bias_s=(float*)(sm+O1_BIAS);
    k1_prefetch_w(sb, 0, ch, tid); CPC();
    const int r=tid>>1, hf=tid&1;
    cvt64(x + (size_t)(r0+r)*128 + hf*64, Ah + r*LDE + hf*64, Al + r*LDE + hf*64);
    if(tid<128){ bias_s[tid]=bq[tid]; bias_s[128+tid]=bk[tid]; bias_s[256+tid]=bv[tid]; }
    for(int m=0;m<3;m++){
        CPW(0); __syncthreads();
        float acc[2][4][4]; zacc(acc);
        warp_pass<272,8>(sb+O1_AH, sb+O1_BH, acc, wr, wc, lane);
        warp_pass<272,8>(sb+O1_AH, sb+O1_BL, acc, wr, wc, lane);
        warp_pass<272,8>(sb+O1_AL, sb+O1_BH, acc, wr, wc, lane);
        __syncthreads();
        float* stag=(float*)(sm+O1_BH);   // overlay consumed W half
        stage_acc(stag, acc, wr, wc, lane);
        __syncthreads();
        if(m==0){
            float tmp[32];
#pragma unroll
            for(int j=0;j<32;j++) tmp[j]=stag[r*LDS2+hf*32+j]+bias_s[ch*64+hf*32+j];
            size_t off=(size_t)(r0+r)*128 + ch*64 + hf*32;
            cvt32(tmp, g_q_hi+off, g_q_lo+off);
        } else {
            const int hl=tid&63, tp=tid>>6, h=ch*64+hl;
            const float bsv=bias_s[m*128+h];
            float tmp[32];
#pragma unroll
            for(int j=0;j<32;j++) tmp[j]=stag[(tp*32+j)*LDS2 + hl]+bsv;
            size_t off=(size_t)((r0>>13)*128+h)*S_LEN + (r0&8191) + tp*32;
            if(m==1) cvt32(tmp, g_k_hi+off, g_k_lo+off);
            else     cvt32(tmp, g_v_hi+off, g_v_lo+off);
        }
        __syncthreads();
        if(m<2){ k1_prefetch_w(sb, m+1, ch, tid); CPC(); }
    }
}

// ============== K2: C'_m (128 v-dims x 64 k-dim half), K=256 pipelined ======
// grid (2, 256): blockIdx.x = k-half -> paired CTAs share v rows via L2.
// Batch order reversed so k2 starts on the k/v freshest in L2 from k1's tail.
#define O2_VH 0
#define O2_VL 18432
#define O2_KH 36864
#define O2_KL 46080
#define K2_BUF 55296
#define SM2 110592

__device__ __forceinline__ void k2_prefetch(unsigned buf, int b, int ch, int t0, int tid){
#pragma unroll
    for(int i=0;i<12;i++){
        int c = tid + 256*i;
        if(c<2048){
            int op=c>>10, e=c&1023, row=e>>3, col8=e&7;
            cpa(buf + (unsigned)op*18432u + (unsigned)(row*144 + col8*16),
                (op? g_v_lo : g_v_hi) + (size_t)(b*128+row)*S_LEN + t0 + col8*8);
        } else {
            int d=c-2048, op=d>>9, e=d&511, row=e>>3, col8=e&7;
            cpa(buf + 36864u + (unsigned)op*9216u + (unsigned)(row*144 + col8*16),
                (op? g_k_lo : g_k_hi) + (size_t)(b*128+ch*64+row)*S_LEN + t0 + col8*8);
        }
    }
}
__global__ __launch_bounds__(256,2) void k2()
{
    extern __shared__ char sm[];
    unsigned sb=smem_u32(sm);
    const int tid=threadIdx.x, lane=tid&31, warp=tid>>5, wr=warp>>1, wc=warp&1;
    const int bm=255-(int)blockIdx.y;   // reversed batch/chunk order
    const int b=bm>>5, mc=bm&31, ch=blockIdx.x;
    const int t0=mc*256;
    k2_prefetch(sb, b, ch, t0, tid); CPC();
    float acc[2][4][4]; zacc(acc);
    for(int qt=0; qt<4; qt++){
        unsigned buf = (qt&1)? K2_BUF : 0u;
        if(qt<3){ k2_prefetch(sb + ((qt&1)?0u:K2_BUF), b, ch, t0+(qt+1)*64, tid); CPC(); CPW(1); }
        else CPW(0);
        __syncthreads();
        warp_pass<144,4>(sb+buf+O2_VH, sb+buf+O2_KH, acc, wr, wc, lane);
        warp_pass<144,4>(sb+buf+O2_VH, sb+buf+O2_KL, acc, wr, wc, lane);
        warp_pass<144,4>(sb+buf+O2_VL, sb+buf+O2_KH, acc, wr, wc, lane);
        __syncthreads();
    }
    float* stag=(float*)sm;
    stage_acc(stag, acc, wr, wc, lane);
    __syncthreads();
    const int r=tid>>1, hf=tid&1;
    float* dst=g_C+((size_t)(b*32+mc)*128+r)*128+ch*64+hf*32;
#pragma unroll
    for(int g=0; g<8; g++){
        float4 o=make_float4(stag[r*LDS2+hf*32+g*4],stag[r*LDS2+hf*32+g*4+1],
                             stag[r*LDS2+hf*32+g*4+2],stag[r*LDS2+hf*32+g*4+3]);
        ((float4*)dst)[g]=o;
    }
}

// ============== K3: out = scale*(q @ Csum^T - edges), 64-col half ===========
// grid (2, 256): blockIdx.x = col half -> paired CTAs share q rows via L2.
// Ascending batch order: starts at b=0 where k2 (reversed) just finished.
#define O3_AH 0
#define O3_AL 34816
#define O3_BH 69632
#define O3_BL 87040
#define O3_EXT 104448
#define SM3 107008

__device__ __forceinline__ void k3_prefetch_q(unsigned sb, size_t qrow0, int tid){
#pragma unroll
    for(int i=0;i<16;i++){
        int c = tid + 256*i;
        int op = c>>11, e=c&2047, row=e>>4, col8=e&15;
        cpa(sb + (unsigned)op*34816u + (unsigned)(row*272 + col8*16),
            (op? g_q_lo : g_q_hi) + (qrow0+row)*128 + col8*8);
    }
}
__global__ __launch_bounds__(256,2) void k3(float* __restrict__ out)
{
    extern __shared__ char sm[];
    unsigned sb=smem_u32(sm);
    const int tid=threadIdx.x, lane=tid&31, warp=tid>>5, wr=warp>>1, wc=warp&1;
    const int idx=blockIdx.y, b=idx>>5, n=idx&31, ch=blockIdx.x;
    __nv_bfloat16* Ah=(__nv_bfloat16*)(sm+O3_AH); __nv_bfloat16* Al=(__nv_bfloat16*)(sm+O3_AL);
    __nv_bfloat16* Bh=(__nv_bfloat16*)(sm+O3_BH); __nv_bfloat16* Bl=(__nv_bfloat16*)(sm+O3_BL);
    float* keL=(float*)(sm+O3_EXT);      float* keR=(float*)(sm+O3_EXT+512);
    float* veL=(float*)(sm+O3_EXT+1024); float* veR=(float*)(sm+O3_EXT+1280);
    float* dls=(float*)(sm+O3_EXT+1536); float* drs=(float*)(sm+O3_EXT+2048);
    const size_t qbase=(size_t)b*S_LEN + n*256;
    k3_prefetch_q(sb, qbase, tid); CPC();
    { // B rows (output cols = hv) = Csum over valid chunks, 64 rows this half
        const int mlo=(n>0)?n-1:0, mhi=(n<31)?n+1:31;
        const int r2=tid>>2, q4=tid&3;
        float s[32];
#pragma unroll
        for(int j=0;j<32;j++) s[j]=0.f;
        for(int mm=mlo; mm<=mhi; mm++){
            const float4* p=(const float4*)(g_C+((size_t)(b*32+mm)*128+ch*64+r2)*128+q4*32);
#pragma unroll
            for(int g=0; g<8; g++){ float4 v=p[g]; s[g*4]+=v.x; s[g*4+1]+=v.y; s[g*4+2]+=v.z; s[g*4+3]+=v.w; }
        }
        cvt32(s, Bh+r2*LDE+q4*32, Bl+r2*LDE+q4*32);
    }
    {
        int teL=n*256-256, teR=n*256+511;
        if(tid<128){
            size_t rb=(size_t)(b*128+tid)*S_LEN;
            keL[tid]=(n>0)? __bfloat162float(g_k_hi[rb+teL])+__bfloat162float(g_k_lo[rb+teL]):0.f;
            keR[tid]=(n<31)? __bfloat162float(g_k_hi[rb+teR])+__bfloat162float(g_k_lo[rb+teR]):0.f;
        } else {
            int j=tid-128;
            if(j<64){
                size_t rb=(size_t)(b*128+ch*64+j)*S_LEN;
                veL[j]=(n>0)? __bfloat162float(g_v_hi[rb+teL])+__bfloat162float(g_v_lo[rb+teL]):0.f;
                veR[j]=(n<31)? __bfloat162float(g_v_hi[rb+teR])+__bfloat162float(g_v_lo[rb+teR]):0.f;
            }
        }
    }
    const float scale=0.08838834764831845f;
    for(int half=0; half<2; half++){
        CPW(0); __syncthreads();
        const int r=tid>>1, hf=tid&1;
        {   // per-row edge dots
            float dl=0.f, dr=0.f;
#pragma unroll 16
            for(int c=0; c<64; c++){
                float q=__bfloat162float(Ah[r*LDE+hf*64+c])+__bfloat162float(Al[r*LDE+hf*64+c]);
                dl+=q*keL[hf*64+c]; dr+=q*keR[hf*64+c];
            }
            dl += __shfl_xor_sync(0xffffffffu, dl, 1);
            dr += __shfl_xor_sync(0xffffffffu, dr, 1);
            if(hf==0){ dls[r]=dl; drs[r]=dr; }
        }
        float acc[2][4][4]; zacc(acc);
        warp_pass<272,8>(sb+O3_AH, sb+O3_BH, acc, wr, wc, lane);
        warp_pass<272,8>(sb+O3_AH, sb+O3_BL, acc, wr, wc, lane);
        warp_pass<272,8>(sb+O3_AL, sb+O3_BH, acc, wr, wc, lane);
        __syncthreads();
        float* stag=(float*)sm;        // overlay A (consumed)
        stage_acc(stag, acc, wr, wc, lane);
        __syncthreads();
        const float dlv=dls[r], drv=drs[r];
        float* op=out+(qbase+half*128+r)*128+ch*64+hf*32;
#pragma unroll
        for(int g=0; g<8; g++){
            int c0=hf*32+g*4;
            float4 o;
            o.x=scale*(stag[r*LDS2+c0+0]-dlv*veL[c0+0]-drv*veR[c0+0]);
            o.y=scale*(stag[r*LDS2+c0+1]-dlv*veL[c0+1]-drv*veR[c0+1]);
            o.z=scale*(stag[r*LDS2+c0+2]-dlv*veL[c0+2]-drv*veR[c0+2]);
            o.w=scale*(stag[r*LDS2+c0+3]-dlv*veL[c0+3]-drv*veR[c0+3]);
            ((float4*)op)[g]=o;
        }
        __syncthreads();
        if(half==0){ k3_prefetch_q(sb, qbase+128, tid); CPC(); }
    }
}

// ---------------------------------------------------------------------------
extern "C" void kernel_launch(void* const* d_in, const int* in_sizes, int n_in,
                              void* d_out, int out_size)
{
    const float* x =(const float*)d_in[0];
    const float* Wq=(const float*)d_in[1]; const float* bq=(const float*)d_in[2];
    const float* Wk=(const float*)d_in[3]; const float* bk=(const float*)d_in[4];
    const float* Wv=(const float*)d_in[5]; const float* bv=(const float*)d_in[6];
    float* out=(float*)d_out;
    cudaFuncSetAttribute(k1, cudaFuncAttributeMaxDynamicSharedMemorySize, SM1);
    cudaFuncSetAttribute(k2, cudaFuncAttributeMaxDynamicSharedMemorySize, SM2);
    cudaFuncSetAttribute(k3, cudaFuncAttributeMaxDynamicSharedMemorySize, SM3);
    k0w<<<3,128>>>(Wq,Wk,Wv);
    k1<<<dim3(2,NROWS/128),256,SM1>>>(x,bq,bk,bv);
    k2<<<dim3(2,NBATCH*NB),256,SM2>>>();
    k3<<<dim3(2,NBATCH*NB),256,SM3>>>(out);
}

// round 8
// speedup vs baseline: 1.3668x; 1.3666x over previous
#include <cuda_runtime.h>
#include <cuda_bf16.h>
#include <cstdint>

#define S_LEN 8192
#define NBATCH 8
#define DIM 128
#define NB 32
#define NROWS (NBATCH*S_LEN)
#define LDE 136      // bf16 elems per 272B operand row

// ---------------- scratch (static device arrays; allocation-free rule) -----
__device__ __align__(16) float g_C[(size_t)NBATCH*NB*DIM*DIM];   // C'[hv][hk] per 256-chunk
__device__ __align__(16) float g_eK[(size_t)NBATCH*NB*2*DIM];    // edge k rows (biased)
__device__ __align__(16) float g_eV[(size_t)NBATCH*NB*2*DIM];
__device__ __align__(16) __nv_bfloat16 g_w_hi[3*DIM*DIM];        // Wq,Wk,Wv
__device__ __align__(16) __nv_bfloat16 g_w_lo[3*DIM*DIM];

// smem region offsets (shared layout for kA/kB)
#define R_XH 0
#define R_XL 34816
#define R_WH 69632
#define R_WL 104448
#define R_VH 139264     // kA: V operand | kB: Msum B operand (hi)
#define R_VL 174080     // (lo)
#define R_EXT 208896

// ---------------- helpers ---------------------------------------------------
__device__ __forceinline__ unsigned smem_u32(const void* p){
    unsigned a; asm("{ .reg .u64 t; cvta.to.shared.u64 t, %1; cvt.u32.u64 %0, t; }":"=r"(a):"l"(p)); return a;
}
__device__ __forceinline__ void ldm4(unsigned* r, unsigned addr){
    asm volatile("ldmatrix.sync.aligned.m8n8.x4.shared.b16 {%0,%1,%2,%3}, [%4];"
        : "=r"(r[0]),"=r"(r[1]),"=r"(r[2]),"=r"(r[3]) : "r"(addr));
}
__device__ __forceinline__ void ldm4t(unsigned* r, unsigned addr){
    asm volatile("ldmatrix.sync.aligned.m8n8.x4.trans.shared.b16 {%0,%1,%2,%3}, [%4];"
        : "=r"(r[0]),"=r"(r[1]),"=r"(r[2]),"=r"(r[3]) : "r"(addr));
}
__device__ __forceinline__ void mma16816(float* d, const unsigned* a, unsigned b0, unsigned b1){
    asm volatile("mma.sync.aligned.m16n8k16.row.col.f32.bf16.bf16.f32 "
        "{%0,%1,%2,%3}, {%4,%5,%6,%7}, {%8,%9}, {%0,%1,%2,%3};"
        : "+f"(d[0]),"+f"(d[1]),"+f"(d[2]),"+f"(d[3])
        : "r"(a[0]),"r"(a[1]),"r"(a[2]),"r"(a[3]), "r"(b0),"r"(b1));
}
__device__ __forceinline__ void cpa(unsigned d, const void* s){
    asm volatile("cp.async.cg.shared.global [%0], [%1], 16;"::"r"(d),"l"(s));
}
#define CPC() asm volatile("cp.async.commit_group;":::"memory")
#define CPW(n) asm volatile("cp.async.wait_group %0;"::"n"(n):"memory")

// non-trans pass: A[t][k] rows t, B[n][k] rows n; D 128x128, warp tile 32x64
__device__ __forceinline__ void passN(unsigned aB, unsigned bB,
                                      float acc[2][8][4], int wr, int wc, int lane){
    unsigned aAddr = aB + (unsigned)((wr*32 + (lane&15))*272) + ((lane>>4)<<4);
    unsigned bAddr = bB + (unsigned)((wc*64 + (lane&7) + ((lane>>4)<<3))*272) + (((lane>>3)&1)<<4);
#pragma unroll
    for(int ks=0; ks<8; ks++){
        unsigned a0[4], a1[4], br[4][4];
        ldm4(a0, aAddr + ks*32);
        ldm4(a1, aAddr + 16*272 + ks*32);
#pragma unroll
        for(int n2=0; n2<4; n2++) ldm4(br[n2], bAddr + n2*16*272 + ks*32);
#pragma unroll
        for(int nt=0; nt<8; nt++){
            unsigned b0 = br[nt>>1][(nt&1)*2], b1 = br[nt>>1][(nt&1)*2+1];
            mma16816(acc[0][nt], a0, b0, b1);
            mma16816(acc[1][nt], a1, b0, b1);
        }
    }
}
// trans pass: operands stored [t][m] / [t][n]; D[m][n] = sum_t A^T B
__device__ __forceinline__ void passT(unsigned aB, unsigned bB,
                                      float acc[2][8][4], int wr, int wc, int lane){
    unsigned row = (unsigned)((lane&7) + ((lane>>4)<<3));
    unsigned csel = (unsigned)((lane>>3)&1);
    unsigned aAddr = aB + row*272 + (unsigned)(wr*32 + csel*8)*2;
    unsigned bAddr = bB + row*272 + (unsigned)(wc*64 + csel*8)*2;
#pragma unroll
    for(int ks=0; ks<8; ks++){
        unsigned base = (unsigned)ks*4352;   // 16 rows * 272B
        unsigned a0[4], a1[4], br[4][4];
        ldm4t(a0, aAddr + base);
        ldm4t(a1, aAddr + base + 32);        // m+16
#pragma unroll
        for(int g=0; g<4; g++) ldm4t(br[g], bAddr + base + g*32);
#pragma unroll
        for(int nt=0; nt<8; nt++){
            int g=nt>>1, sub=nt&1;
            unsigned b0 = br[g][sub], b1 = br[g][sub+2];
            mma16816(acc[0][nt], a0, b0, b1);
            mma16816(acc[1][nt], a1, b0, b1);
        }
    }
}
__device__ __forceinline__ void zacc(float acc[2][8][4]){
#pragma unroll
    for(int a=0;a<2;a++)
#pragma unroll
    for(int b=0;b<8;b++){acc[a][b][0]=acc[a][b][1]=acc[a][b][2]=acc[a][b][3]=0.f;}
}
// frag -> bf16 hi/lo operand smem [row][col], +bias; optional edge row save (f32)
__device__ __forceinline__ void frag_to_op(float acc[2][8][4], __nv_bfloat16* Oh, __nv_bfloat16* Ol,
                                           const float* bias, float* erow, int ewhich,
                                           int wr, int wc, int lane){
#pragma unroll
    for(int mt=0; mt<2; mt++)
#pragma unroll
    for(int nt=0; nt<8; nt++){
        int c = wc*64 + (lane&3)*2 + nt*8;
        float b0=bias[c], b1=bias[c+1];
#pragma unroll
        for(int hh=0; hh<2; hh++){
            int r = wr*32 + (lane>>2) + mt*16 + hh*8;
            float v0 = acc[mt][nt][hh*2]   + b0;
            float v1 = acc[mt][nt][hh*2+1] + b1;
            __nv_bfloat162 H, L;
            H.x=__float2bfloat16_rn(v0); L.x=__float2bfloat16_rn(v0-__bfloat162float(H.x));
            H.y=__float2bfloat16_rn(v1); L.y=__float2bfloat16_rn(v1-__bfloat162float(H.y));
            *(unsigned*)&Oh[r*LDE+c] = *(unsigned*)&H;
            *(unsigned*)&Ol[r*LDE+c] = *(unsigned*)&L;
            if(erow && ((ewhich==0 && r==0) || (ewhich==1 && r==127))){
                erow[c]=v0; erow[c+1]=v1;
            }
        }
    }
}
__device__ __forceinline__ void cvt64(const float* s, __nv_bfloat16* dh, __nv_bfloat16* dl){
#pragma unroll
    for(int g=0; g<8; g++){
        float4 a=((const float4*)s)[2*g], b=((const float4*)s)[2*g+1];
        float f[8]={a.x,a.y,a.z,a.w,b.x,b.y,b.z,b.w};
        __align__(16) __nv_bfloat16 h[8], l[8];
#pragma unroll
        for(int i=0;i<8;i++){ h[i]=__float2bfloat16_rn(f[i]); l[i]=__float2bfloat16_rn(f[i]-__bfloat162float(h[i])); }
        ((uint4*)dh)[g]=*(const uint4*)h; ((uint4*)dl)[g]=*(const uint4*)l;
    }
}
// full-W prefetch into R_WH/R_WL
__device__ __forceinline__ void pref_w(unsigned sb, int widx, int tid){
#pragma unroll
    for(int i=0;i<16;i++){
        int c = tid + 256*i;
        int op = c>>11, e=c&2047, row=e>>4, col8=e&15;
        cpa(sb + R_WH + (unsigned)op*34816u + (unsigned)(row*272 + col8*16),
            (op? g_w_lo : g_w_hi) + (size_t)widx*16384 + (size_t)row*128 + col8*8);
    }
}

// ============== kz: zero g_C ================================================
__global__ void kz(){
    size_t i = (size_t)blockIdx.x*256 + threadIdx.x;
    ((uint4*)g_C)[i] = make_uint4(0,0,0,0);
}
// ============== k0w: pre-convert W ==========================================
__global__ void k0w(const float* __restrict__ Wq, const float* __restrict__ Wk,
                    const float* __restrict__ Wv){
    const float* W = blockIdx.x==0?Wq:(blockIdx.x==1?Wk:Wv);
    int h = threadIdx.x;
    size_t o = (size_t)blockIdx.x*16384 + (size_t)h*128;
    cvt64(W + (size_t)h*128,      g_w_hi+o,    g_w_lo+o);
    cvt64(W + (size_t)h*128 + 64, g_w_hi+o+64, g_w_lo+o+64);
}

// ============== kA: x -> v,k proj -> C' chunk outer-product =================
#define A_BIASV (R_EXT)
#define A_BIASK (R_EXT+512)
#define SMA (R_EXT+1024)
__global__ __launch_bounds__(256,1) void kA(const float* __restrict__ x,
    const float* __restrict__ bk, const float* __restrict__ bv)
{
    extern __shared__ char sm[];
    unsigned sb = smem_u32(sm);
    const int tid=threadIdx.x, lane=tid&31, warp=tid>>5, wr=warp>>1, wc=warp&1;
    const int b=blockIdx.x>>6, j=blockIdx.x&63, m=j>>1, p=j&1;
    const size_t rbase=(size_t)b*S_LEN + j*128;
    __nv_bfloat16* Xh=(__nv_bfloat16*)(sm+R_XH); __nv_bfloat16* Xl=(__nv_bfloat16*)(sm+R_XL);
    __nv_bfloat16* Vh=(__nv_bfloat16*)(sm+R_VH); __nv_bfloat16* Vl=(__nv_bfloat16*)(sm+R_VL);
    float* biasv=(float*)(sm+A_BIASV); float* biask=(float*)(sm+A_BIASK);
    pref_w(sb, 2, tid); CPC();                       // Wv
    const int r=tid>>1, hf=tid&1;
    cvt64(x + (rbase+r)*128 + hf*64, Xh + r*LDE + hf*64, Xl + r*LDE + hf*64);
    if(tid<128) biasv[tid]=bv[tid]; else biask[tid-128]=bk[tid-128];
    CPW(0); __syncthreads();
    // v = x @ Wv^T
    float acc[2][8][4]; zacc(acc);
    passN(sb+R_XH, sb+R_WH, acc, wr, wc, lane);
    passN(sb+R_XH, sb+R_WL, acc, wr, wc, lane);
    passN(sb+R_XL, sb+R_WH, acc, wr, wc, lane);
    frag_to_op(acc, Vh, Vl, biasv, g_eV + ((size_t)(b*32+m)*2+p)*128, p, wr, wc, lane);
    __syncthreads();                                  // WB free, V visible later
    pref_w(sb, 1, tid); CPC(); CPW(0); __syncthreads();  // Wk
    // k = x @ Wk^T
    zacc(acc);
    passN(sb+R_XH, sb+R_WH, acc, wr, wc, lane);
    passN(sb+R_XH, sb+R_WL, acc, wr, wc, lane);
    passN(sb+R_XL, sb+R_WH, acc, wr, wc, lane);
    __syncthreads();                                  // all warps done reading X
    frag_to_op(acc, Xh, Xl, biask, g_eK + ((size_t)(b*32+m)*2+p)*128, p, wr, wc, lane); // K overlays X
    __syncthreads();
    // C'[hv][hk] += sum_t v[t][hv] * k[t][hk]   (trans loads)
    zacc(acc);
    passT(sb+R_VH, sb+R_XH, acc, wr, wc, lane);
    passT(sb+R_VH, sb+R_XL, acc, wr, wc, lane);
    passT(sb+R_VL, sb+R_XH, acc, wr, wc, lane);
    float* cb = g_C + (size_t)(b*32+m)*16384;
#pragma unroll
    for(int mt=0; mt<2; mt++)
#pragma unroll
    for(int nt=0; nt<8; nt++){
        int c = wc*64 + (lane&3)*2 + nt*8;
#pragma unroll
        for(int hh=0; hh<2; hh++){
            int rr = wr*32 + (lane>>2) + mt*16 + hh*8;
            atomicAdd(cb + rr*128 + c,     acc[mt][nt][hh*2]);
            atomicAdd(cb + rr*128 + c + 1, acc[mt][nt][hh*2+1]);
        }
    }
}

// ============== kB: q proj + out = scale*(q @ Msum^T - edges) ===============
#define B_BIASQ (R_EXT)
#define B_KEL (R_EXT+512)
#define B_KER (R_EXT+1024)
#define B_VEL (R_EXT+1536)
#define B_VER (R_EXT+2048)
#define B_DLS (R_EXT+2560)
#define B_DRS (R_EXT+3072)
#define SMB (R_EXT+3584)
__global__ __launch_bounds__(256,1) void kB(float* __restrict__ out,
    const float* __restrict__ x, const float* __restrict__ bq)
{
    extern __shared__ char sm[];
    unsigned sb = smem_u32(sm);
    const int tid=threadIdx.x, lane=tid&31, warp=tid>>5, wr=warp>>1, wc=warp&1;
    const int b=blockIdx.x>>5, n=blockIdx.x&31;
    __nv_bfloat16* Xh=(__nv_bfloat16*)(sm+R_XH); __nv_bfloat16* Xl=(__nv_bfloat16*)(sm+R_XL);
    __nv_bfloat16* Bh=(__nv_bfloat16*)(sm+R_VH); __nv_bfloat16* Bl=(__nv_bfloat16*)(sm+R_VL);
    float* biasq=(float*)(sm+B_BIASQ);
    float* keL=(float*)(sm+B_KEL); float* keR=(float*)(sm+B_KER);
    float* veL=(float*)(sm+B_VEL); float* veR=(float*)(sm+B_VER);
    float* dls=(float*)(sm+B_DLS); float* drs=(float*)(sm+B_DRS);
    const size_t qbase=(size_t)b*S_LEN + n*256;
    pref_w(sb, 0, tid); CPC();                       // Wq
    const int r=tid>>1, hf=tid&1;
    {   // Msum = sum of valid C' chunks -> bf16 hi/lo B operand rows hv
        const int mlo=(n>0)?n-1:0, mhi=(n<31)?n+1:31;
        float s[64];
#pragma unroll
        for(int q2=0;q2<64;q2++) s[q2]=0.f;
        for(int mm=mlo; mm<=mhi; mm++){
            const float4* pp=(const float4*)(g_C+(size_t)(b*32+mm)*16384 + r*128 + hf*64);
#pragma unroll
            for(int g=0; g<16; g++){ float4 v=pp[g]; s[g*4]+=v.x; s[g*4+1]+=v.y; s[g*4+2]+=v.z; s[g*4+3]+=v.w; }
        }
        // reuse cvt path (no bias): pack into B operand row r (=hv), cols hk
        __align__(16) __nv_bfloat16 h8[8], l8[8];
#pragma unroll
        for(int g=0; g<8; g++){
#pragma unroll
            for(int i=0;i<8;i++){
                float v=s[g*8+i];
                h8[i]=__float2bfloat16_rn(v); l8[i]=__float2bfloat16_rn(v-__bfloat162float(h8[i]));
            }
            ((uint4*)(Bh + r*LDE + hf*64))[g]=*(const uint4*)h8;
            ((uint4*)(Bl + r*LDE + hf*64))[g]=*(const uint4*)l8;
        }
    }
    if(tid<128){
        biasq[tid]=bq[tid];
        keL[tid]=(n>0)?  g_eK[((size_t)(b*32+n-1)*2+0)*128+tid] : 0.f;
        keR[tid]=(n<31)? g_eK[((size_t)(b*32+n+1)*2+1)*128+tid] : 0.f;
    } else {
        int t2=tid-128;
        veL[t2]=(n>0)?  g_eV[((size_t)(b*32+n-1)*2+0)*128+t2] : 0.f;
        veR[t2]=(n<31)? g_eV[((size_t)(b*32+n+1)*2+1)*128+t2] : 0.f;
    }
    CPW(0); __syncthreads();
    const float scale=0.08838834764831845f;
    for(int half=0; half<2; half++){
        // load x for this q half
        cvt64(x + (qbase+half*128+r)*128 + hf*64, Xh + r*LDE + hf*64, Xl + r*LDE + hf*64);
        __syncthreads();
        // q = x @ Wq^T
        float acc[2][8][4]; zacc(acc);
        passN(sb+R_XH, sb+R_WH, acc, wr, wc, lane);
        passN(sb+R_XH, sb+R_WL, acc, wr, wc, lane);
        passN(sb+R_XL, sb+R_WH, acc, wr, wc, lane);
        __syncthreads();                          // done reading X
        frag_to_op(acc, Xh, Xl, biasq, (float*)0, 0, wr, wc, lane);  // q overlays X
        __syncthreads();
        {   // per-row edge dots
            float dl=0.f, dr=0.f;
#pragma unroll 16
            for(int c=0; c<64; c++){
                float qv=__bfloat162float(Xh[r*LDE+hf*64+c])+__bfloat162float(Xl[r*LDE+hf*64+c]);
                dl+=qv*keL[hf*64+c]; dr+=qv*keR[hf*64+c];
            }
            dl += __shfl_xor_sync(0xffffffffu, dl, 1);
            dr += __shfl_xor_sync(0xffffffffu, dr, 1);
            if(hf==0){ dls[r]=dl; drs[r]=dr; }
        }
        // out = q @ Msum^T
        zacc(acc);
        passN(sb+R_XH, sb+R_VH, acc, wr, wc, lane);
        passN(sb+R_XH, sb+R_VL, acc, wr, wc, lane);
        passN(sb+R_XL, sb+R_VH, acc, wr, wc, lane);
        __syncthreads();                          // dls/drs visible
        float* ob = out + (qbase+half*128)*128;
#pragma unroll
        for(int mt=0; mt<2; mt++)
#pragma unroll
        for(int nt=0; nt<8; nt++){
            int c = wc*64 + (lane&3)*2 + nt*8;
#pragma unroll
            for(int hh=0; hh<2; hh++){
                int rr = wr*32 + (lane>>2) + mt*16 + hh*8;
                float dlv=dls[rr], drv=drs[rr];
                float2 o;
                o.x = scale*(acc[mt][nt][hh*2]   - dlv*veL[c]   - drv*veR[c]);
                o.y = scale*(acc[mt][nt][hh*2+1] - dlv*veL[c+1] - drv*veR[c+1]);
                *(float2*)(ob + (size_t)rr*128 + c) = o;
            }
        }
        __syncthreads();                          // before next half reloads X
    }
}

// ---------------------------------------------------------------------------
extern "C" void kernel_launch(void* const* d_in, const int* in_sizes, int n_in,
                              void* d_out, int out_size)
{
    const float* x =(const float*)d_in[0];
    const float* Wq=(const float*)d_in[1]; const float* bq=(const float*)d_in[2];
    const float* Wk=(const float*)d_in[3]; const float* bk=(const float*)d_in[4];
    const float* Wv=(const float*)d_in[5]; const float* bv=(const float*)d_in[6];
    float* out=(float*)d_out;
    cudaFuncSetAttribute(kA, cudaFuncAttributeMaxDynamicSharedMemorySize, SMA);
    cudaFuncSetAttribute(kB, cudaFuncAttributeMaxDynamicSharedMemorySize, SMB);
    kz<<<(NBATCH*NB*DIM*DIM)/(4*256),256>>>();
    k0w<<<3,128>>>(Wq,Wk,Wv);
    kA<<<NBATCH*64,256,SMA>>>(x,bk,bv);
    kB<<<NBATCH*NB,256,SMB>>>(out,x,bq);
}

// round 9
// speedup vs baseline: 1.5639x; 1.1443x over previous
#include <cuda_runtime.h>
#include <cuda_bf16.h>
#include <cstdint>

#define S_LEN 8192
#define NBATCH 8
#define DIM 128
#define NB 32
#define NROWS (NBATCH*S_LEN)
#define LDE 136      // bf16 elems per 272B operand row

// ---------------- scratch (static device arrays; allocation-free rule) -----
__device__ __align__(16) float g_C[(size_t)NBATCH*NB*DIM*DIM];   // C'[hv][hk] per 256-chunk
__device__ __align__(16) float g_eK[(size_t)NBATCH*NB*2*DIM];    // edge k rows (biased)
__device__ __align__(16) float g_eV[(size_t)NBATCH*NB*2*DIM];
__device__ __align__(16) __nv_bfloat16 g_w_hi[3*DIM*DIM];        // Wq,Wk,Wv (row-major [h][d])
__device__ __align__(16) __nv_bfloat16 g_w_lo[3*DIM*DIM];
__device__ __align__(16) __nv_bfloat16 g_wt_hi[DIM*DIM];         // Wq^T ([d][hq])
__device__ __align__(16) __nv_bfloat16 g_wt_lo[DIM*DIM];

// smem regions (both kernels): 3 x 68KB operand regions + ext
#define R_X 0
#define R_XH 0
#define R_XL 34816
#define R_W 69632
#define R_WH 69632
#define R_WL 104448
#define R_V 139264
#define R_VH 139264
#define R_VL 174080
#define R_EXT 208896
#define SMEM_SZ (R_EXT+3072)

// ---------------- helpers ---------------------------------------------------
__device__ __forceinline__ unsigned smem_u32(const void* p){
    unsigned a; asm("{ .reg .u64 t; cvta.to.shared.u64 t, %1; cvt.u32.u64 %0, t; }":"=r"(a):"l"(p)); return a;
}
__device__ __forceinline__ void ldm4(unsigned* r, unsigned addr){
    asm volatile("ldmatrix.sync.aligned.m8n8.x4.shared.b16 {%0,%1,%2,%3}, [%4];"
        : "=r"(r[0]),"=r"(r[1]),"=r"(r[2]),"=r"(r[3]) : "r"(addr));
}
__device__ __forceinline__ void ldm4t(unsigned* r, unsigned addr){
    asm volatile("ldmatrix.sync.aligned.m8n8.x4.trans.shared.b16 {%0,%1,%2,%3}, [%4];"
        : "=r"(r[0]),"=r"(r[1]),"=r"(r[2]),"=r"(r[3]) : "r"(addr));
}
__device__ __forceinline__ void mma16816(float* d, const unsigned* a, unsigned b0, unsigned b1){
    asm volatile("mma.sync.aligned.m16n8k16.row.col.f32.bf16.bf16.f32 "
        "{%0,%1,%2,%3}, {%4,%5,%6,%7}, {%8,%9}, {%0,%1,%2,%3};"
        : "+f"(d[0]),"+f"(d[1]),"+f"(d[2]),"+f"(d[3])
        : "r"(a[0]),"r"(a[1]),"r"(a[2]),"r"(a[3]), "r"(b0),"r"(b1));
}
__device__ __forceinline__ void cpa(unsigned d, const void* s){
    asm volatile("cp.async.cg.shared.global [%0], [%1], 16;"::"r"(d),"l"(s));
}
#define CPC() asm volatile("cp.async.commit_group;":::"memory")
#define CPW(n) asm volatile("cp.async.wait_group %0;"::"n"(n):"memory")

__device__ __forceinline__ void passN(unsigned aB, unsigned bB,
                                      float acc[2][8][4], int wr, int wc, int lane){
    unsigned aAddr = aB + (unsigned)((wr*32 + (lane&15))*272) + ((lane>>4)<<4);
    unsigned bAddr = bB + (unsigned)((wc*64 + (lane&7) + ((lane>>4)<<3))*272) + (((lane>>3)&1)<<4);
#pragma unroll
    for(int ks=0; ks<8; ks++){
        unsigned a0[4], a1[4], br[4][4];
        ldm4(a0, aAddr + ks*32);
        ldm4(a1, aAddr + 16*272 + ks*32);
#pragma unroll
        for(int n2=0; n2<4; n2++) ldm4(br[n2], bAddr + n2*16*272 + ks*32);
#pragma unroll
        for(int nt=0; nt<8; nt++){
            unsigned b0 = br[nt>>1][(nt&1)*2], b1 = br[nt>>1][(nt&1)*2+1];
            mma16816(acc[0][nt], a0, b0, b1);
            mma16816(acc[1][nt], a1, b0, b1);
        }
    }
}
__device__ __forceinline__ void passT(unsigned aB, unsigned bB,
                                      float acc[2][8][4], int wr, int wc, int lane){
    unsigned row = (unsigned)((lane&7) + ((lane>>4)<<3));
    unsigned csel = (unsigned)((lane>>3)&1);
    unsigned aAddr = aB + row*272 + (unsigned)(wr*32 + csel*8)*2;
    unsigned bAddr = bB + row*272 + (unsigned)(wc*64 + csel*8)*2;
#pragma unroll
    for(int ks=0; ks<8; ks++){
        unsigned base = (unsigned)ks*4352;
        unsigned a0[4], a1[4], br[4][4];
        ldm4t(a0, aAddr + base);
        ldm4t(a1, aAddr + base + 32);
#pragma unroll
        for(int g=0; g<4; g++) ldm4t(br[g], bAddr + base + g*32);
#pragma unroll
        for(int nt=0; nt<8; nt++){
            int g=nt>>1, sub=nt&1;
            unsigned b0 = br[g][sub], b1 = br[g][sub+2];
            mma16816(acc[0][nt], a0, b0, b1);
            mma16816(acc[1][nt], a1, b0, b1);
        }
    }
}
__device__ __forceinline__ void zacc(float acc[2][8][4]){
#pragma unroll
    for(int a=0;a<2;a++)
#pragma unroll
    for(int b=0;b<8;b++){acc[a][b][0]=acc[a][b][1]=acc[a][b][2]=acc[a][b][3]=0.f;}
}
__device__ __forceinline__ void frag_to_op(float acc[2][8][4], __nv_bfloat16* Oh, __nv_bfloat16* Ol,
                                           const float* bias, float* erow, int ewhich,
                                           int wr, int wc, int lane){
#pragma unroll
    for(int mt=0; mt<2; mt++)
#pragma unroll
    for(int nt=0; nt<8; nt++){
        int c = wc*64 + (lane&3)*2 + nt*8;
        float b0 = bias? bias[c]   : 0.f;
        float b1 = bias? bias[c+1] : 0.f;
#pragma unroll
        for(int hh=0; hh<2; hh++){
            int r = wr*32 + (lane>>2) + mt*16 + hh*8;
            float v0 = acc[mt][nt][hh*2]   + b0;
            float v1 = acc[mt][nt][hh*2+1] + b1;
            __nv_bfloat162 H, L;
            H.x=__float2bfloat16_rn(v0); L.x=__float2bfloat16_rn(v0-__bfloat162float(H.x));
            H.y=__float2bfloat16_rn(v1); L.y=__float2bfloat16_rn(v1-__bfloat162float(H.y));
            *(unsigned*)&Oh[r*LDE+c] = *(unsigned*)&H;
            *(unsigned*)&Ol[r*LDE+c] = *(unsigned*)&L;
            if(erow && ((ewhich==0 && r==0) || (ewhich==1 && r==127))){
                erow[c]=v0; erow[c+1]=v1;
            }
        }
    }
}
__device__ __forceinline__ void cvt64(const float* s, __nv_bfloat16* dh, __nv_bfloat16* dl){
#pragma unroll
    for(int g=0; g<8; g++){
        float4 a=((const float4*)s)[2*g], b=((const float4*)s)[2*g+1];
        float f[8]={a.x,a.y,a.z,a.w,b.x,b.y,b.z,b.w};
        __align__(16) __nv_bfloat16 h[8], l[8];
#pragma unroll
        for(int i=0;i<8;i++){ h[i]=__float2bfloat16_rn(f[i]); l[i]=__float2bfloat16_rn(f[i]-__bfloat162float(h[i])); }
        ((uint4*)dh)[g]=*(const uint4*)h; ((uint4*)dl)[g]=*(const uint4*)l;
    }
}
// prefetch one W matrix (hi+lo) into region reg (bf16 operand layout)
__device__ __forceinline__ void pref_wmat(unsigned sb, unsigned reg,
                                          const __nv_bfloat16* wh, const __nv_bfloat16* wl, int tid){
#pragma unroll
    for(int i=0;i<16;i++){
        int c = tid + 256*i;
        int op = c>>11, e=c&2047, row=e>>4, col8=e&15;
        cpa(sb + reg + (unsigned)op*34816u + (unsigned)(row*272 + col8*16),
            (op? wl : wh) + (size_t)row*128 + col8*8);
    }
}

// ============== kz: zero g_C ================================================
__global__ void kz(){
    size_t i = (size_t)blockIdx.x*256 + threadIdx.x;
    ((uint4*)g_C)[i] = make_uint4(0,0,0,0);
}
// ============== k0w: pre-convert W (+ Wq^T) =================================
__global__ void k0w(const float* __restrict__ Wq, const float* __restrict__ Wk,
                    const float* __restrict__ Wv){
    int h = threadIdx.x;
    if(blockIdx.x<3){
        const float* W = blockIdx.x==0?Wq:(blockIdx.x==1?Wk:Wv);
        size_t o = (size_t)blockIdx.x*16384 + (size_t)h*128;
        cvt64(W + (size_t)h*128,      g_w_hi+o,    g_w_lo+o);
        cvt64(W + (size_t)h*128 + 64, g_w_hi+o+64, g_w_lo+o+64);
    } else {
        float tmp[128];
#pragma unroll 8
        for(int hq=0; hq<128; hq++) tmp[hq] = Wq[(size_t)hq*128 + h];
        cvt64(tmp,    g_wt_hi + (size_t)h*128,    g_wt_lo + (size_t)h*128);
        cvt64(tmp+64, g_wt_hi + (size_t)h*128+64, g_wt_lo + (size_t)h*128+64);
    }
}

// ============== kA: x -> v,k proj -> C' chunk outer-product =================
#define A_BIASV (R_EXT)
#define A_BIASK (R_EXT+512)
__global__ __launch_bounds__(256,1) void kA(const float* __restrict__ x,
    const float* __restrict__ bk, const float* __restrict__ bv)
{
    extern __shared__ char sm[];
    unsigned sb = smem_u32(sm);
    const int tid=threadIdx.x, lane=tid&31, warp=tid>>5, wr=warp>>1, wc=warp&1;
    const int b=blockIdx.x>>6, j=blockIdx.x&63, m=j>>1, p=j&1;
    const size_t rbase=(size_t)b*S_LEN + j*128;
    __nv_bfloat16* Xh=(__nv_bfloat16*)(sm+R_XH); __nv_bfloat16* Xl=(__nv_bfloat16*)(sm+R_XL);
    float* biasv=(float*)(sm+A_BIASV); float* biask=(float*)(sm+A_BIASK);
    // both W matrices up-front: Wv -> R_W, Wk -> R_V
    pref_wmat(sb, R_W, g_w_hi+2*16384, g_w_lo+2*16384, tid);
    pref_wmat(sb, R_V, g_w_hi+1*16384, g_w_lo+1*16384, tid);
    CPC();
    const int r=tid>>1, hf=tid&1;
    cvt64(x + (rbase+r)*128 + hf*64, Xh + r*LDE + hf*64, Xl + r*LDE + hf*64);
    if(tid<128) biasv[tid]=bv[tid]; else biask[tid-128]=bk[tid-128];
    CPW(0); __syncthreads();
    // v = x @ Wv^T
    float acc[2][8][4]; zacc(acc);
    passN(sb+R_XH, sb+R_WH, acc, wr, wc, lane);
    passN(sb+R_XH, sb+R_WL, acc, wr, wc, lane);
    passN(sb+R_XL, sb+R_WH, acc, wr, wc, lane);
    __syncthreads();                                   // all warps done reading Wv
    frag_to_op(acc, (__nv_bfloat16*)(sm+R_WH), (__nv_bfloat16*)(sm+R_WL),
               biasv, g_eV + ((size_t)(b*32+m)*2+p)*128, p, wr, wc, lane);  // V -> R_W
    __syncthreads();
    // k = x @ Wk^T  (Wk lives in R_V)
    zacc(acc);
    passN(sb+R_XH, sb+R_VH, acc, wr, wc, lane);
    passN(sb+R_XH, sb+R_VL, acc, wr, wc, lane);
    passN(sb+R_XL, sb+R_VH, acc, wr, wc, lane);
    __syncthreads();                                   // done reading x + Wk
    frag_to_op(acc, Xh, Xl, biask, g_eK + ((size_t)(b*32+m)*2+p)*128, p, wr, wc, lane); // K -> R_X
    __syncthreads();
    // C'[hv][hk] += sum_t v[t][hv] * k[t][hk]
    zacc(acc);
    passT(sb+R_WH, sb+R_XH, acc, wr, wc, lane);
    passT(sb+R_WH, sb+R_XL, acc, wr, wc, lane);
    passT(sb+R_WL, sb+R_XH, acc, wr, wc, lane);
    float* cb = g_C + (size_t)(b*32+m)*16384;
#pragma unroll
    for(int mt=0; mt<2; mt++)
#pragma unroll
    for(int nt=0; nt<8; nt++){
        int c = wc*64 + (lane&3)*2 + nt*8;
#pragma unroll
        for(int hh=0; hh<2; hh++){
            int rr = wr*32 + (lane>>2) + mt*16 + hh*8;
            atomicAdd(cb + rr*128 + c,     acc[mt][nt][hh*2]);
            atomicAdd(cb + rr*128 + c + 1, acc[mt][nt][hh*2+1]);
        }
    }
}

// ============== kB: G = M~ @ Wq ; out = scale*(x@G^T + c) ==================
#define B_KEL (R_EXT)
#define B_KER (R_EXT+512)
#define B_VEL (R_EXT+1024)
#define B_VER (R_EXT+1536)
#define B_BQ  (R_EXT+2048)
#define B_CS  (R_EXT+2560)
// f32 x staging: 128 rows, stride 528B (132 f32) = 67584B, fits a 68K region
__device__ __forceinline__ void stage_x(unsigned reg, const float* x, size_t row0, int tid){
#pragma unroll
    for(int i=0;i<16;i++){
        int c = tid + 256*i;
        int row=c>>5, col16=c&31;
        cpa(reg + (unsigned)(row*528 + col16*16), x + (row0+row)*128 + col16*4);
    }
}
__global__ __launch_bounds__(256,1) void kB(float* __restrict__ out,
    const float* __restrict__ x, const float* __restrict__ bq)
{
    extern __shared__ char sm[];
    unsigned sb = smem_u32(sm);
    const int tid=threadIdx.x, lane=tid&31, warp=tid>>5, wr=warp>>1, wc=warp&1;
    const int b=blockIdx.x>>5, n=blockIdx.x&31;
    __nv_bfloat16* Xh=(__nv_bfloat16*)(sm+R_XH); __nv_bfloat16* Xl=(__nv_bfloat16*)(sm+R_XL);
    __nv_bfloat16* Vh=(__nv_bfloat16*)(sm+R_VH); __nv_bfloat16* Vl=(__nv_bfloat16*)(sm+R_VL);
    float* keL=(float*)(sm+B_KEL); float* keR=(float*)(sm+B_KER);
    float* veL=(float*)(sm+B_VEL); float* veR=(float*)(sm+B_VER);
    float* bqs=(float*)(sm+B_BQ);  float* cs=(float*)(sm+B_CS);
    const size_t qbase=(size_t)b*S_LEN + n*256;
    pref_wmat(sb, R_W, g_wt_hi, g_wt_lo, tid); CPC();       // group0: Wq^T
    stage_x(sb+R_X, x, qbase, tid); CPC();                  // group1: x half0 f32
    // edges + bq
    if(tid<128){
        bqs[tid]=bq[tid];
        keL[tid]=(n>0)?  g_eK[((size_t)(b*32+n-1)*2+0)*128+tid] : 0.f;
        keR[tid]=(n<31)? g_eK[((size_t)(b*32+n+1)*2+1)*128+tid] : 0.f;
    } else {
        int t2=tid-128;
        veL[t2]=(n>0)?  g_eV[((size_t)(b*32+n-1)*2+0)*128+t2] : 0.f;
        veR[t2]=(n<31)? g_eV[((size_t)(b*32+n+1)*2+1)*128+t2] : 0.f;
    }
    __syncthreads();
    // gather M~ = Csum - veL(x)keL - veR(x)keR ; c[hv] = bq . M~[hv]
    const int r=tid>>1, hf=tid&1;
    {
        const int mlo=(n>0)?n-1:0, mhi=(n<31)?n+1:31;
        float s[64];
#pragma unroll
        for(int q2=0;q2<64;q2++) s[q2]=0.f;
        for(int mm=mlo; mm<=mhi; mm++){
            const float4* pp=(const float4*)(g_C+(size_t)(b*32+mm)*16384 + r*128 + hf*64);
#pragma unroll
            for(int g=0; g<16; g++){ float4 v=pp[g]; s[g*4]+=v.x; s[g*4+1]+=v.y; s[g*4+2]+=v.z; s[g*4+3]+=v.w; }
        }
        float vl=veL[r], vr=veR[r], cpart=0.f;
#pragma unroll
        for(int q2=0;q2<64;q2++){
            int col=hf*64+q2;
            s[q2] -= vl*keL[col] + vr*keR[col];
            cpart += bqs[col]*s[q2];
        }
        cpart += __shfl_xor_sync(0xffffffffu, cpart, 1);
        if(hf==0) cs[r]=cpart;
        // cvt M~ row r -> R_V operand (A for G pass)
        __align__(16) __nv_bfloat16 h8[8], l8[8];
#pragma unroll
        for(int g=0; g<8; g++){
#pragma unroll
            for(int i=0;i<8;i++){
                float v=s[g*8+i];
                h8[i]=__float2bfloat16_rn(v); l8[i]=__float2bfloat16_rn(v-__bfloat162float(h8[i]));
            }
            ((uint4*)(Vh + r*LDE + hf*64))[g]=*(const uint4*)h8;
            ((uint4*)(Vl + r*LDE + hf*64))[g]=*(const uint4*)l8;
        }
    }
    CPW(1);                 // Wq^T ready (x0 still in flight)
    __syncthreads();
    // G[hv][d] = M~ @ Wq : A=R_V (M~), B=R_W (Wq^T rows d)
    float acc[2][8][4]; zacc(acc);
    passN(sb+R_VH, sb+R_WH, acc, wr, wc, lane);
    passN(sb+R_VH, sb+R_WL, acc, wr, wc, lane);
    passN(sb+R_VL, sb+R_WH, acc, wr, wc, lane);
    __syncthreads();                                   // done reading M~ + Wq^T
    stage_x(sb+R_W, x, qbase+128, tid); CPC();         // group2: x half1 f32 -> R_W (dead)
    frag_to_op(acc, Vh, Vl, (const float*)0, (float*)0, 0, wr, wc, lane);  // G -> R_V
    __syncthreads();
    const float scale=0.08838834764831845f;
    for(int half=0; half<2; half++){
        if(half==0) CPW(1); else CPW(0);
        // cvt staged f32 x -> bf16 operand in R_X (read-all, sync, write)
        {
            const float* st = (const float*)(sm + (half==0? R_X : R_W));
            float v[64];
            const float4* p4 = (const float4*)(st + r*132 + hf*64);
#pragma unroll
            for(int g=0; g<16; g++){ float4 t=p4[g]; v[g*4]=t.x; v[g*4+1]=t.y; v[g*4+2]=t.z; v[g*4+3]=t.w; }
            __syncthreads();
            __align__(16) __nv_bfloat16 h8[8], l8[8];
#pragma unroll
            for(int g=0; g<8; g++){
#pragma unroll
                for(int i=0;i<8;i++){
                    float vv=v[g*8+i];
                    h8[i]=__float2bfloat16_rn(vv); l8[i]=__float2bfloat16_rn(vv-__bfloat162float(h8[i]));
                }
                ((uint4*)(Xh + r*LDE + hf*64))[g]=*(const uint4*)h8;
                ((uint4*)(Xl + r*LDE + hf*64))[g]=*(const uint4*)l8;
            }
        }
        __syncthreads();
        // out_half = x @ G^T
        zacc(acc);
        passN(sb+R_XH, sb+R_VH, acc, wr, wc, lane);
        passN(sb+R_XH, sb+R_VL, acc, wr, wc, lane);
        passN(sb+R_XL, sb+R_VH, acc, wr, wc, lane);
        float* ob = out + (qbase+half*128)*128;
#pragma unroll
        for(int mt=0; mt<2; mt++)
#pragma unroll
        for(int nt=0; nt<8; nt++){
            int c = wc*64 + (lane&3)*2 + nt*8;
            float c0=cs[c], c1=cs[c+1];
#pragma unroll
            for(int hh=0; hh<2; hh++){
                int rr = wr*32 + (lane>>2) + mt*16 + hh*8;
                float2 o;
                o.x = scale*(acc[mt][nt][hh*2]   + c0);
                o.y = scale*(acc[mt][nt][hh*2+1] + c1);
                *(float2*)(ob + (size_t)rr*128 + c) = o;
            }
        }
        __syncthreads();   // X region reuse next half
    }
}

// ---------------------------------------------------------------------------
extern "C" void kernel_launch(void* const* d_in, const int* in_sizes, int n_in,
                              void* d_out, int out_size)
{
    const float* x =(const float*)d_in[0];
    const float* Wq=(const float*)d_in[1]; const float* bq=(const float*)d_in[2];
    const float* Wk=(const float*)d_in[3]; const float* bk=(const float*)d_in[4];
    const float* Wv=(const float*)d_in[5]; const float* bv=(const float*)d_in[6];
    float* out=(float*)d_out;
    cudaFuncSetAttribute(kA, cudaFuncAttributeMaxDynamicSharedMemorySize, SMEM_SZ);
    cudaFuncSetAttribute(kB, cudaFuncAttributeMaxDynamicSharedMemorySize, SMEM_SZ);
    kz<<<(NBATCH*NB*DIM*DIM)/(4*256),256>>>();
    k0w<<<4,128>>>(Wq,Wk,Wv);
    kA<<<NBATCH*64,256,SMEM_SZ>>>(x,bk,bv);
    kB<<<NBATCH*NB,256,SMEM_SZ>>>(out,x,bq);
}

// round 10
// speedup vs baseline: 1.6602x; 1.0616x over previous
#include <cuda_runtime.h>
#include <cuda_bf16.h>
#include <cstdint>

#define S_LEN 8192
#define NBATCH 8
#define DIM 128
#define NB 32
#define NROWS (NBATCH*S_LEN)
#define LDE 136      // bf16 elems per 272B operand row

// ---------------- scratch (static device arrays; allocation-free rule) -----
__device__ __align__(16) float g_C[(size_t)NBATCH*NB*DIM*DIM];   // C'[hv][hk] per 256-chunk
__device__ __align__(16) float g_eK[(size_t)NBATCH*NB*2*DIM];    // edge k rows (biased)
__device__ __align__(16) float g_eV[(size_t)NBATCH*NB*2*DIM];
__device__ __align__(16) __nv_bfloat16 g_w_hi[3*DIM*DIM];        // Wq,Wk,Wv (row-major [h][d])
__device__ __align__(16) __nv_bfloat16 g_w_lo[3*DIM*DIM];
__device__ __align__(16) __nv_bfloat16 g_wt_hi[DIM*DIM];         // Wq^T ([d][hq])
__device__ __align__(16) __nv_bfloat16 g_wt_lo[DIM*DIM];

// smem regions (both kernels): 3 x 68KB operand regions + ext
#define R_X 0
#define R_XH 0
#define R_XL 34816
#define R_W 69632
#define R_WH 69632
#define R_WL 104448
#define R_V 139264
#define R_VH 139264
#define R_VL 174080
#define R_EXT 208896
#define SMEM_SZ (R_EXT+3072)

// ---------------- helpers ---------------------------------------------------
__device__ __forceinline__ unsigned smem_u32(const void* p){
    unsigned a; asm("{ .reg .u64 t; cvta.to.shared.u64 t, %1; cvt.u32.u64 %0, t; }":"=r"(a):"l"(p)); return a;
}
__device__ __forceinline__ void ldm4(unsigned* r, unsigned addr){
    asm volatile("ldmatrix.sync.aligned.m8n8.x4.shared.b16 {%0,%1,%2,%3}, [%4];"
        : "=r"(r[0]),"=r"(r[1]),"=r"(r[2]),"=r"(r[3]) : "r"(addr));
}
__device__ __forceinline__ void ldm4t(unsigned* r, unsigned addr){
    asm volatile("ldmatrix.sync.aligned.m8n8.x4.trans.shared.b16 {%0,%1,%2,%3}, [%4];"
        : "=r"(r[0]),"=r"(r[1]),"=r"(r[2]),"=r"(r[3]) : "r"(addr));
}
__device__ __forceinline__ void mma16816(float* d, const unsigned* a, unsigned b0, unsigned b1){
    asm volatile("mma.sync.aligned.m16n8k16.row.col.f32.bf16.bf16.f32 "
        "{%0,%1,%2,%3}, {%4,%5,%6,%7}, {%8,%9}, {%0,%1,%2,%3};"
        : "+f"(d[0]),"+f"(d[1]),"+f"(d[2]),"+f"(d[3])
        : "r"(a[0]),"r"(a[1]),"r"(a[2]),"r"(a[3]), "r"(b0),"r"(b1));
}
__device__ __forceinline__ void cpa(unsigned d, const void* s){
    asm volatile("cp.async.cg.shared.global [%0], [%1], 16;"::"r"(d),"l"(s));
}
#define CPC() asm volatile("cp.async.commit_group;":::"memory")
#define CPW(n) asm volatile("cp.async.wait_group %0;"::"n"(n):"memory")

// merged 3-pass (AhBh + AhBl + AlBh), non-trans operands [row][k]
__device__ __forceinline__ void pass3N(unsigned aH, unsigned aL, unsigned bH, unsigned bL,
                                       float acc[2][8][4], int wr, int wc, int lane){
    unsigned aOff = (unsigned)((wr*32 + (lane&15))*272) + ((lane>>4)<<4);
    unsigned bOff = (unsigned)((wc*64 + (lane&7) + ((lane>>4)<<3))*272) + (((lane>>3)&1)<<4);
#pragma unroll
    for(int ks=0; ks<8; ks++){
        unsigned ah0[4], ah1[4], al0[4], al1[4], bh[4][4], bl[4][4];
        ldm4(ah0, aH + aOff + ks*32);
        ldm4(ah1, aH + aOff + 16*272 + ks*32);
        ldm4(al0, aL + aOff + ks*32);
        ldm4(al1, aL + aOff + 16*272 + ks*32);
#pragma unroll
        for(int n2=0; n2<4; n2++){
            ldm4(bh[n2], bH + bOff + n2*16*272 + ks*32);
            ldm4(bl[n2], bL + bOff + n2*16*272 + ks*32);
        }
#pragma unroll
        for(int nt=0; nt<8; nt++){
            unsigned b0 = bh[nt>>1][(nt&1)*2], b1 = bh[nt>>1][(nt&1)*2+1];
            mma16816(acc[0][nt], ah0, b0, b1);
            mma16816(acc[1][nt], ah1, b0, b1);
        }
#pragma unroll
        for(int nt=0; nt<8; nt++){
            unsigned c0 = bl[nt>>1][(nt&1)*2], c1 = bl[nt>>1][(nt&1)*2+1];
            mma16816(acc[0][nt], ah0, c0, c1);
            mma16816(acc[1][nt], ah1, c0, c1);
        }
#pragma unroll
        for(int nt=0; nt<8; nt++){
            unsigned b0 = bh[nt>>1][(nt&1)*2], b1 = bh[nt>>1][(nt&1)*2+1];
            mma16816(acc[0][nt], al0, b0, b1);
            mma16816(acc[1][nt], al1, b0, b1);
        }
    }
}
// merged 3-pass, trans operands stored [t][m]/[t][n]
__device__ __forceinline__ void pass3T(unsigned aH, unsigned aL, unsigned bH, unsigned bL,
                                       float acc[2][8][4], int wr, int wc, int lane){
    unsigned row = (unsigned)((lane&7) + ((lane>>4)<<3));
    unsigned csel = (unsigned)((lane>>3)&1);
    unsigned aOff = row*272 + (unsigned)(wr*32 + csel*8)*2;
    unsigned bOff = row*272 + (unsigned)(wc*64 + csel*8)*2;
#pragma unroll
    for(int ks=0; ks<8; ks++){
        unsigned base = (unsigned)ks*4352;
        unsigned ah0[4], ah1[4], al0[4], al1[4], bh[4][4], bl[4][4];
        ldm4t(ah0, aH + aOff + base);
        ldm4t(ah1, aH + aOff + base + 32);
        ldm4t(al0, aL + aOff + base);
        ldm4t(al1, aL + aOff + base + 32);
#pragma unroll
        for(int g=0; g<4; g++){
            ldm4t(bh[g], bH + bOff + base + g*32);
            ldm4t(bl[g], bL + bOff + base + g*32);
        }
#pragma unroll
        for(int nt=0; nt<8; nt++){
            int g=nt>>1, sub=nt&1;
            unsigned b0 = bh[g][sub], b1 = bh[g][sub+2];
            mma16816(acc[0][nt], ah0, b0, b1);
            mma16816(acc[1][nt], ah1, b0, b1);
        }
#pragma unroll
        for(int nt=0; nt<8; nt++){
            int g=nt>>1, sub=nt&1;
            unsigned c0 = bl[g][sub], c1 = bl[g][sub+2];
            mma16816(acc[0][nt], ah0, c0, c1);
            mma16816(acc[1][nt], ah1, c0, c1);
        }
#pragma unroll
        for(int nt=0; nt<8; nt++){
            int g=nt>>1, sub=nt&1;
            unsigned b0 = bh[g][sub], b1 = bh[g][sub+2];
            mma16816(acc[0][nt], al0, b0, b1);
            mma16816(acc[1][nt], al1, b0, b1);
        }
    }
}
__device__ __forceinline__ void zacc(float acc[2][8][4]){
#pragma unroll
    for(int a=0;a<2;a++)
#pragma unroll
    for(int b=0;b<8;b++){acc[a][b][0]=acc[a][b][1]=acc[a][b][2]=acc[a][b][3]=0.f;}
}
__device__ __forceinline__ void frag_to_op(float acc[2][8][4], __nv_bfloat16* Oh, __nv_bfloat16* Ol,
                                           const float* bias, float* erow, int ewhich,
                                           int wr, int wc, int lane){
#pragma unroll
    for(int mt=0; mt<2; mt++)
#pragma unroll
    for(int nt=0; nt<8; nt++){
        int c = wc*64 + (lane&3)*2 + nt*8;
        float b0 = bias? bias[c]   : 0.f;
        float b1 = bias? bias[c+1] : 0.f;
#pragma unroll
        for(int hh=0; hh<2; hh++){
            int r = wr*32 + (lane>>2) + mt*16 + hh*8;
            float v0 = acc[mt][nt][hh*2]   + b0;
            float v1 = acc[mt][nt][hh*2+1] + b1;
            __nv_bfloat162 H, L;
            H.x=__float2bfloat16_rn(v0); L.x=__float2bfloat16_rn(v0-__bfloat162float(H.x));
            H.y=__float2bfloat16_rn(v1); L.y=__float2bfloat16_rn(v1-__bfloat162float(H.y));
            *(unsigned*)&Oh[r*LDE+c] = *(unsigned*)&H;
            *(unsigned*)&Ol[r*LDE+c] = *(unsigned*)&L;
            if(erow && ((ewhich==0 && r==0) || (ewhich==1 && r==127))){
                erow[c]=v0; erow[c+1]=v1;
            }
        }
    }
}
__device__ __forceinline__ void cvt64(const float* s, __nv_bfloat16* dh, __nv_bfloat16* dl){
#pragma unroll
    for(int g=0; g<8; g++){
        float4 a=((const float4*)s)[2*g], b=((const float4*)s)[2*g+1];
        float f[8]={a.x,a.y,a.z,a.w,b.x,b.y,b.z,b.w};
        __align__(16) __nv_bfloat16 h[8], l[8];
#pragma unroll
        for(int i=0;i<8;i++){ h[i]=__float2bfloat16_rn(f[i]); l[i]=__float2bfloat16_rn(f[i]-__bfloat162float(h[i])); }
        ((uint4*)dh)[g]=*(const uint4*)h; ((uint4*)dl)[g]=*(const uint4*)l;
    }
}
__device__ __forceinline__ void pref_wmat(unsigned sb, unsigned reg,
                                          const __nv_bfloat16* wh, const __nv_bfloat16* wl, int tid){
#pragma unroll
    for(int i=0;i<16;i++){
        int c = tid + 256*i;
        int op = c>>11, e=c&2047, row=e>>4, col8=e&15;
        cpa(sb + reg + (unsigned)op*34816u + (unsigned)(row*272 + col8*16),
            (op? wl : wh) + (size_t)row*128 + col8*8);
    }
}

// ============== kz: zero g_C ================================================
__global__ void kz(){
    size_t i = (size_t)blockIdx.x*256 + threadIdx.x;
    ((uint4*)g_C)[i] = make_uint4(0,0,0,0);
}
// ============== k0w: pre-convert W (+ Wq^T) =================================
__global__ void k0w(const float* __restrict__ Wq, const float* __restrict__ Wk,
                    const float* __restrict__ Wv){
    int h = threadIdx.x;
    if(blockIdx.x<3){
        const float* W = blockIdx.x==0?Wq:(blockIdx.x==1?Wk:Wv);
        size_t o = (size_t)blockIdx.x*16384 + (size_t)h*128;
        cvt64(W + (size_t)h*128,      g_w_hi+o,    g_w_lo+o);
        cvt64(W + (size_t)h*128 + 64, g_w_hi+o+64, g_w_lo+o+64);
    } else {
        float tmp[128];
#pragma unroll 8
        for(int hq=0; hq<128; hq++) tmp[hq] = Wq[(size_t)hq*128 + h];
        cvt64(tmp,    g_wt_hi + (size_t)h*128,    g_wt_lo + (size_t)h*128);
        cvt64(tmp+64, g_wt_hi + (size_t)h*128+64, g_wt_lo + (size_t)h*128+64);
    }
}

// ============== kA: x -> v,k proj -> C' chunk outer-product =================
#define A_BIASV (R_EXT)
#define A_BIASK (R_EXT+512)
__global__ __launch_bounds__(256,1) void kA(const float* __restrict__ x,
    const float* __restrict__ bk, const float* __restrict__ bv)
{
    extern __shared__ char sm[];
    unsigned sb = smem_u32(sm);
    const int tid=threadIdx.x, lane=tid&31, warp=tid>>5, wr=warp>>1, wc=warp&1;
    const int b=blockIdx.x>>6, j=blockIdx.x&63, m=j>>1, p=j&1;
    const size_t rbase=(size_t)b*S_LEN + j*128;
    __nv_bfloat16* Xh=(__nv_bfloat16*)(sm+R_XH); __nv_bfloat16* Xl=(__nv_bfloat16*)(sm+R_XL);
    float* biasv=(float*)(sm+A_BIASV); float* biask=(float*)(sm+A_BIASK);
    pref_wmat(sb, R_W, g_w_hi+2*16384, g_w_lo+2*16384, tid);   // Wv
    pref_wmat(sb, R_V, g_w_hi+1*16384, g_w_lo+1*16384, tid);   // Wk
    CPC();
    const int r=tid>>1, hf=tid&1;
    cvt64(x + (rbase+r)*128 + hf*64, Xh + r*LDE + hf*64, Xl + r*LDE + hf*64);
    if(tid<128) biasv[tid]=bv[tid]; else biask[tid-128]=bk[tid-128];
    CPW(0); __syncthreads();
    // v = x @ Wv^T
    float acc[2][8][4]; zacc(acc);
    pass3N(sb+R_XH, sb+R_XL, sb+R_WH, sb+R_WL, acc, wr, wc, lane);
    __syncthreads();                                   // all warps done reading Wv
    frag_to_op(acc, (__nv_bfloat16*)(sm+R_WH), (__nv_bfloat16*)(sm+R_WL),
               biasv, g_eV + ((size_t)(b*32+m)*2+p)*128, p, wr, wc, lane);  // V -> R_W
    __syncthreads();
    // k = x @ Wk^T  (Wk in R_V)
    zacc(acc);
    pass3N(sb+R_XH, sb+R_XL, sb+R_VH, sb+R_VL, acc, wr, wc, lane);
    __syncthreads();                                   // done reading x + Wk
    frag_to_op(acc, Xh, Xl, biask, g_eK + ((size_t)(b*32+m)*2+p)*128, p, wr, wc, lane); // K -> R_X
    __syncthreads();
    // C'[hv][hk] += sum_t v[t][hv] * k[t][hk]
    zacc(acc);
    pass3T(sb+R_WH, sb+R_WL, sb+R_XH, sb+R_XL, acc, wr, wc, lane);
    float* cb = g_C + (size_t)(b*32+m)*16384;
#pragma unroll
    for(int mt=0; mt<2; mt++)
#pragma unroll
    for(int nt=0; nt<8; nt++){
        int c = wc*64 + (lane&3)*2 + nt*8;
#pragma unroll
        for(int hh=0; hh<2; hh++){
            int rr = wr*32 + (lane>>2) + mt*16 + hh*8;
            atomicAdd(cb + rr*128 + c,     acc[mt][nt][hh*2]);
            atomicAdd(cb + rr*128 + c + 1, acc[mt][nt][hh*2+1]);
        }
    }
}

// ============== kB: G = M~ @ Wq ; out = scale*(x@G^T + c) ==================
#define B_KEL (R_EXT)
#define B_KER (R_EXT+512)
#define B_VEL (R_EXT+1024)
#define B_VER (R_EXT+1536)
#define B_BQ  (R_EXT+2048)
#define B_CS  (R_EXT+2560)
__device__ __forceinline__ void stage_x(unsigned reg, const float* x, size_t row0, int tid){
#pragma unroll
    for(int i=0;i<16;i++){
        int c = tid + 256*i;
        int row=c>>5, col16=c&31;
        cpa(reg + (unsigned)(row*528 + col16*16), x + (row0+row)*128 + col16*4);
    }
}
__global__ __launch_bounds__(256,1) void kB(float* __restrict__ out,
    const float* __restrict__ x, const float* __restrict__ bq)
{
    extern __shared__ char sm[];
    unsigned sb = smem_u32(sm);
    const int tid=threadIdx.x, lane=tid&31, warp=tid>>5, wr=warp>>1, wc=warp&1;
    const int b=blockIdx.x>>5, n=blockIdx.x&31;
    __nv_bfloat16* Xh=(__nv_bfloat16*)(sm+R_XH); __nv_bfloat16* Xl=(__nv_bfloat16*)(sm+R_XL);
    __nv_bfloat16* Vh=(__nv_bfloat16*)(sm+R_VH); __nv_bfloat16* Vl=(__nv_bfloat16*)(sm+R_VL);
    float* keL=(float*)(sm+B_KEL); float* keR=(float*)(sm+B_KER);
    float* veL=(float*)(sm+B_VEL); float* veR=(float*)(sm+B_VER);
    float* bqs=(float*)(sm+B_BQ);  float* cs=(float*)(sm+B_CS);
    const size_t qbase=(size_t)b*S_LEN + n*256;
    pref_wmat(sb, R_W, g_wt_hi, g_wt_lo, tid); CPC();       // g0: Wq^T
    stage_x(sb+R_X, x, qbase, tid); CPC();                  // g1: x half0 f32
    if(tid<128){
        bqs[tid]=bq[tid];
        keL[tid]=(n>0)?  g_eK[((size_t)(b*32+n-1)*2+0)*128+tid] : 0.f;
        keR[tid]=(n<31)? g_eK[((size_t)(b*32+n+1)*2+1)*128+tid] : 0.f;
    } else {
        int t2=tid-128;
        veL[t2]=(n>0)?  g_eV[((size_t)(b*32+n-1)*2+0)*128+t2] : 0.f;
        veR[t2]=(n<31)? g_eV[((size_t)(b*32+n+1)*2+1)*128+t2] : 0.f;
    }
    __syncthreads();
    const int r=tid>>1, hf=tid&1;
    {   // M~ = Csum - veL(x)keL - veR(x)keR ; c[hv] = bq . M~[hv] ; cvt -> R_V
        const int mlo=(n>0)?n-1:0, mhi=(n<31)?n+1:31;
        float s[64];
#pragma unroll
        for(int q2=0;q2<64;q2++) s[q2]=0.f;
        for(int mm=mlo; mm<=mhi; mm++){
            const float4* pp=(const float4*)(g_C+(size_t)(b*32+mm)*16384 + r*128 + hf*64);
#pragma unroll
            for(int g=0; g<16; g++){ float4 v=pp[g]; s[g*4]+=v.x; s[g*4+1]+=v.y; s[g*4+2]+=v.z; s[g*4+3]+=v.w; }
        }
        float vl=veL[r], vr=veR[r], cpart=0.f;
#pragma unroll
        for(int q2=0;q2<64;q2++){
            int col=hf*64+q2;
            s[q2] -= vl*keL[col] + vr*keR[col];
            cpart += bqs[col]*s[q2];
        }
        cpart += __shfl_xor_sync(0xffffffffu, cpart, 1);
        if(hf==0) cs[r]=cpart;
        __align__(16) __nv_bfloat16 h8[8], l8[8];
#pragma unroll
        for(int g=0; g<8; g++){
#pragma unroll
            for(int i=0;i<8;i++){
                float v=s[g*8+i];
                h8[i]=__float2bfloat16_rn(v); l8[i]=__float2bfloat16_rn(v-__bfloat162float(h8[i]));
            }
            ((uint4*)(Vh + r*LDE + hf*64))[g]=*(const uint4*)h8;
            ((uint4*)(Vl + r*LDE + hf*64))[g]=*(const uint4*)l8;
        }
    }
    CPW(0);                       // Wq^T + x0 in
    {   // cvt x0 f32(R_X staging) -> bf16 operand (in-place): read, sync, write
        float v[64];
        const float4* p4 = (const float4*)((const float*)(sm+R_X) + r*132 + hf*64);
#pragma unroll
        for(int g=0; g<16; g++){ float4 t=p4[g]; v[g*4]=t.x; v[g*4+1]=t.y; v[g*4+2]=t.z; v[g*4+3]=t.w; }
        __syncthreads();
        __align__(16) __nv_bfloat16 h8[8], l8[8];
#pragma unroll
        for(int g=0; g<8; g++){
#pragma unroll
            for(int i=0;i<8;i++){
                float vv=v[g*8+i];
                h8[i]=__float2bfloat16_rn(vv); l8[i]=__float2bfloat16_rn(vv-__bfloat162float(h8[i]));
            }
            ((uint4*)(Xh + r*LDE + hf*64))[g]=*(const uint4*)h8;
            ((uint4*)(Xl + r*LDE + hf*64))[g]=*(const uint4*)l8;
        }
    }
    __syncthreads();              // M~, x0 operands ready
    // G[hv][d] = M~ @ Wq : A=R_V, B=R_W
    float acc[2][8][4]; zacc(acc);
    pass3N(sb+R_VH, sb+R_VL, sb+R_WH, sb+R_WL, acc, wr, wc, lane);
    __syncthreads();              // done reading M~ + Wq^T
    stage_x(sb+R_W, x, qbase+128, tid); CPC();   // g2: x half1 -> R_W (dead)
    frag_to_op(acc, Vh, Vl, (const float*)0, (float*)0, 0, wr, wc, lane);    // G -> R_V
    __syncthreads();
    const float scale=0.08838834764831845f;
#pragma unroll
    for(int half=0; half<2; half++){
        // out_half = x @ G^T
        zacc(acc);
        pass3N(sb+R_XH, sb+R_XL, sb+R_VH, sb+R_VL, acc, wr, wc, lane);
        float* ob = out + (qbase+half*128)*128;
#pragma unroll
        for(int mt=0; mt<2; mt++)
#pragma unroll
        for(int nt=0; nt<8; nt++){
            int c = wc*64 + (lane&3)*2 + nt*8;
            float c0=cs[c], c1=cs[c+1];
#pragma unroll
            for(int hh=0; hh<2; hh++){
                int rr = wr*32 + (lane>>2) + mt*16 + hh*8;
                float2 o;
                o.x = scale*(acc[mt][nt][hh*2]   + c0);
                o.y = scale*(acc[mt][nt][hh*2+1] + c1);
                *(float2*)(ob + (size_t)rr*128 + c) = o;
            }
        }
        if(half==0){
            CPW(0); __syncthreads();          // x1 staged; out0 done reading R_X
            float v[64];
            const float4* p4 = (const float4*)((const float*)(sm+R_W) + r*132 + hf*64);
#pragma unroll
            for(int g=0; g<16; g++){ float4 t=p4[g]; v[g*4]=t.x; v[g*4+1]=t.y; v[g*4+2]=t.z; v[g*4+3]=t.w; }
            __align__(16) __nv_bfloat16 h8[8], l8[8];
#pragma unroll
            for(int g=0; g<8; g++){
#pragma unroll
                for(int i=0;i<8;i++){
                    float vv=v[g*8+i];
                    h8[i]=__float2bfloat16_rn(vv); l8[i]=__float2bfloat16_rn(vv-__bfloat162float(h8[i]));
                }
                ((uint4*)(Xh + r*LDE + hf*64))[g]=*(const uint4*)h8;
                ((uint4*)(Xl + r*LDE + hf*64))[g]=*(const uint4*)l8;
            }
            __syncthreads();
        }
    }
}

// ---------------------------------------------------------------------------
extern "C" void kernel_launch(void* const* d_in, const int* in_sizes, int n_in,
                              void* d_out, int out_size)
{
    const float* x =(const float*)d_in[0];
    const float* Wq=(const float*)d_in[1]; const float* bq=(const float*)d_in[2];
    const float* Wk=(const float*)d_in[3]; const float* bk=(const float*)d_in[4];
    const float* Wv=(const float*)d_in[5]; const float* bv=(const float*)d_in[6];
    float* out=(float*)d_out;
    cudaFuncSetAttribute(kA, cudaFuncAttributeMaxDynamicSharedMemorySize, SMEM_SZ);
    cudaFuncSetAttribute(kB, cudaFuncAttributeMaxDynamicSharedMemorySize, SMEM_SZ);
    kz<<<(NBATCH*NB*DIM*DIM)/(4*256),256>>>();
    k0w<<<4,128>>>(Wq,Wk,Wv);
    kA<<<NBATCH*64,256,SMEM_SZ>>>(x,bk,bv);
    kB<<<NBATCH*NB,256,SMEM_SZ>>>(out,x,bq);
}